// round 1
// baseline (speedup 1.0000x reference)
#include <cuda_runtime.h>
#include <math.h>

#define S_LEN    4096
#define DM       1024
#define NHEADS   16
#define HDIM     64

// Scratch (allocation-free rule: __device__ globals)
__device__ float g_Q[S_LEN * DM];
__device__ float g_K[S_LEN * DM];
__device__ float g_V[S_LEN * DM];
__device__ float g_A[S_LEN * DM];
__device__ float g_invfreq[HDIM / 2];

// ---------------------------------------------------------------------------
// inv_freq in double precision (one tiny launch; matches reference closely)
// ---------------------------------------------------------------------------
__global__ void freq_kernel() {
    int j = threadIdx.x;           // 0..31
    if (j < HDIM / 2) {
        double e = -(double)j / 32.0 * log(10000.0);
        g_invfreq[j] = (float)exp(e);
    }
}

// ---------------------------------------------------------------------------
// GEMM (NT): C[M,N] = A[M,K] * B[N,K]^T    (row-major, K contiguous both)
// 128x128x16 tile, 256 threads, 8x8 microtile per thread
// ---------------------------------------------------------------------------
__global__ __launch_bounds__(256) void gemm_nt(
    const float* __restrict__ A, const float* __restrict__ B,
    float* __restrict__ C, int M, int N, int K)
{
    __shared__ __align__(16) float As[16][128];
    __shared__ __align__(16) float Bs[16][128];

    const int tid  = threadIdx.x;
    const int tx   = tid & 15;        // n sub-tile
    const int ty   = tid >> 4;        // m sub-tile
    const int row0 = blockIdx.y * 128;
    const int col0 = blockIdx.x * 128;

    float acc[8][8];
#pragma unroll
    for (int i = 0; i < 8; i++)
#pragma unroll
        for (int j = 0; j < 8; j++) acc[i][j] = 0.f;

    const int lm = tid >> 2;          // 0..63  (row within tile)
    const int lk = (tid & 3) * 4;     // 0,4,8,12 (k offset)
    const float* Aptr = A + (size_t)(row0 + lm) * K + lk;
    const float* Bptr = B + (size_t)(col0 + lm) * K + lk;
    const size_t astr = (size_t)64 * K;

    for (int k0 = 0; k0 < K; k0 += 16) {
        float4 a0 = *(const float4*)(Aptr + k0);
        float4 a1 = *(const float4*)(Aptr + k0 + astr);
        float4 b0 = *(const float4*)(Bptr + k0);
        float4 b1 = *(const float4*)(Bptr + k0 + astr);

        As[lk + 0][lm]      = a0.x; As[lk + 1][lm]      = a0.y;
        As[lk + 2][lm]      = a0.z; As[lk + 3][lm]      = a0.w;
        As[lk + 0][lm + 64] = a1.x; As[lk + 1][lm + 64] = a1.y;
        As[lk + 2][lm + 64] = a1.z; As[lk + 3][lm + 64] = a1.w;
        Bs[lk + 0][lm]      = b0.x; Bs[lk + 1][lm]      = b0.y;
        Bs[lk + 2][lm]      = b0.z; Bs[lk + 3][lm]      = b0.w;
        Bs[lk + 0][lm + 64] = b1.x; Bs[lk + 1][lm + 64] = b1.y;
        Bs[lk + 2][lm + 64] = b1.z; Bs[lk + 3][lm + 64] = b1.w;
        __syncthreads();

#pragma unroll
        for (int kk = 0; kk < 16; kk++) {
            float a[8], b[8];
            float4 t;
            t = *(const float4*)&As[kk][ty * 8];     a[0]=t.x; a[1]=t.y; a[2]=t.z; a[3]=t.w;
            t = *(const float4*)&As[kk][ty * 8 + 4]; a[4]=t.x; a[5]=t.y; a[6]=t.z; a[7]=t.w;
            t = *(const float4*)&Bs[kk][tx * 8];     b[0]=t.x; b[1]=t.y; b[2]=t.z; b[3]=t.w;
            t = *(const float4*)&Bs[kk][tx * 8 + 4]; b[4]=t.x; b[5]=t.y; b[6]=t.z; b[7]=t.w;
#pragma unroll
            for (int i = 0; i < 8; i++)
#pragma unroll
                for (int j = 0; j < 8; j++) acc[i][j] += a[i] * b[j];
        }
        __syncthreads();
    }

#pragma unroll
    for (int i = 0; i < 8; i++) {
        float* Cp = C + (size_t)(row0 + ty * 8 + i) * N + col0 + tx * 8;
        float4 o0 = make_float4(acc[i][0], acc[i][1], acc[i][2], acc[i][3]);
        float4 o1 = make_float4(acc[i][4], acc[i][5], acc[i][6], acc[i][7]);
        *(float4*)(Cp)     = o0;
        *(float4*)(Cp + 4) = o1;
    }
}

// ---------------------------------------------------------------------------
// RoPE: interleaved (even,odd) rotation applied in-place to Q and K
// ---------------------------------------------------------------------------
__global__ __launch_bounds__(256) void rope_kernel(
    float* __restrict__ Q, float* __restrict__ Kd, const int* __restrict__ pos)
{
    int idx = blockIdx.x * blockDim.x + threadIdx.x;     // over S * 512 pairs
    if (idx >= S_LEN * (DM / 2)) return;
    int s = idx >> 9;        // row
    int p = idx & 511;       // pair within row
    int h = p >> 5;
    int j = p & 31;
    float ang = (float)pos[s] * g_invfreq[j];
    float sn, cs;
    sincosf(ang, &sn, &cs);
    size_t base = (size_t)s * DM + h * HDIM + 2 * j;
    float2 qv = *(float2*)(Q + base);
    float2 kv = *(float2*)(Kd + base);
    *(float2*)(Q + base)  = make_float2(qv.x * cs - qv.y * sn, qv.x * sn + qv.y * cs);
    *(float2*)(Kd + base) = make_float2(kv.x * cs - kv.y * sn, kv.x * sn + kv.y * cs);
}

// ---------------------------------------------------------------------------
// Causal flash attention. 1 query row per thread, 128 queries per CTA,
// 64-key K/V tiles in smem. Running-max online softmax (rescale on new max).
// ---------------------------------------------------------------------------
__global__ __launch_bounds__(128) void flash_attn(
    const float* __restrict__ Q, const float* __restrict__ K,
    const float* __restrict__ V, float* __restrict__ O)
{
    __shared__ __align__(16) float Ks[64][64];
    __shared__ __align__(16) float Vs[64][64];

    const int h     = blockIdx.y;
    const int qbase = blockIdx.x * 128;
    const int tid   = threadIdx.x;
    const int s     = qbase + tid;

    float q[HDIM], acc[HDIM];
    const float* Qp = Q + (size_t)s * DM + h * HDIM;
#pragma unroll
    for (int d = 0; d < HDIM; d += 4) {
        float4 t = *(const float4*)(Qp + d);
        q[d]   = t.x * 0.125f;  q[d+1] = t.y * 0.125f;
        q[d+2] = t.z * 0.125f;  q[d+3] = t.w * 0.125f;
        acc[d] = acc[d+1] = acc[d+2] = acc[d+3] = 0.f;
    }

    float m = -1e30f;
    float l = 0.f;
    const int kend = qbase + 128;           // keys needed: t <= s < kend

    for (int kt = 0; kt < kend; kt += 64) {
        __syncthreads();
        for (int i = tid; i < 64 * 64 / 4; i += 128) {
            int r = i >> 4;
            int c = (i & 15) << 2;
            size_t off = (size_t)(kt + r) * DM + h * HDIM + c;
            *(float4*)&Ks[r][c] = *(const float4*)(K + off);
            *(float4*)&Vs[r][c] = *(const float4*)(V + off);
        }
        __syncthreads();

        int jmax = s - kt + 1;
        if (jmax > 64) jmax = 64;
        for (int j = 0; j < jmax; j++) {
            // dot(q, K[j]) with 4 independent accumulation chains
            float s0 = 0.f, s1 = 0.f, s2 = 0.f, s3 = 0.f;
#pragma unroll
            for (int d = 0; d < HDIM; d += 16) {
                float4 k0 = *(const float4*)&Ks[j][d];
                float4 k1 = *(const float4*)&Ks[j][d + 4];
                float4 k2 = *(const float4*)&Ks[j][d + 8];
                float4 k3 = *(const float4*)&Ks[j][d + 12];
                s0 += q[d]    * k0.x + q[d+1]  * k0.y + q[d+2]  * k0.z + q[d+3]  * k0.w;
                s1 += q[d+4]  * k1.x + q[d+5]  * k1.y + q[d+6]  * k1.z + q[d+7]  * k1.w;
                s2 += q[d+8]  * k2.x + q[d+9]  * k2.y + q[d+10] * k2.z + q[d+11] * k2.w;
                s3 += q[d+12] * k3.x + q[d+13] * k3.y + q[d+14] * k3.z + q[d+15] * k3.w;
            }
            float sc = (s0 + s1) + (s2 + s3);

            if (sc > m) {                    // rare: rescale running state
                float scale = __expf(m - sc);
                m = sc;
                l *= scale;
#pragma unroll
                for (int d = 0; d < HDIM; d++) acc[d] *= scale;
            }
            float pj = __expf(sc - m);
            l += pj;
#pragma unroll
            for (int d = 0; d < HDIM; d += 4) {
                float4 vv = *(const float4*)&Vs[j][d];
                acc[d]   += pj * vv.x;  acc[d+1] += pj * vv.y;
                acc[d+2] += pj * vv.z;  acc[d+3] += pj * vv.w;
            }
        }
    }

    float rcp = 1.0f / l;
    float* Op = O + (size_t)s * DM + h * HDIM;
#pragma unroll
    for (int d = 0; d < HDIM; d += 4) {
        *(float4*)(Op + d) = make_float4(acc[d] * rcp, acc[d+1] * rcp,
                                         acc[d+2] * rcp, acc[d+3] * rcp);
    }
}

// ---------------------------------------------------------------------------
// Launcher
// ---------------------------------------------------------------------------
extern "C" void kernel_launch(void* const* d_in, const int* in_sizes, int n_in,
                              void* d_out, int out_size)
{
    const float* x  = (const float*)d_in[0];
    const float* Wq = (const float*)d_in[1];
    const float* Wk = (const float*)d_in[2];
    const float* Wv = (const float*)d_in[3];
    const float* Wo = (const float*)d_in[4];
    const int*  pos = (const int*)  d_in[5];
    float* out = (float*)d_out;

    float *Qb, *Kb, *Vb, *Ab;
    cudaGetSymbolAddress((void**)&Qb, g_Q);
    cudaGetSymbolAddress((void**)&Kb, g_K);
    cudaGetSymbolAddress((void**)&Vb, g_V);
    cudaGetSymbolAddress((void**)&Ab, g_A);

    dim3 ggrid(DM / 128, S_LEN / 128);       // (8, 32)

    freq_kernel<<<1, 32>>>();
    gemm_nt<<<ggrid, 256>>>(x, Wq, Qb, S_LEN, DM, DM);
    gemm_nt<<<ggrid, 256>>>(x, Wk, Kb, S_LEN, DM, DM);
    gemm_nt<<<ggrid, 256>>>(x, Wv, Vb, S_LEN, DM, DM);

    int rope_threads = S_LEN * (DM / 2);
    rope_kernel<<<(rope_threads + 255) / 256, 256>>>(Qb, Kb, pos);

    flash_attn<<<dim3(S_LEN / 128, NHEADS), 128>>>(Qb, Kb, Vb, Ab);

    gemm_nt<<<ggrid, 256>>>(Ab, Wo, out, S_LEN, DM, DM);
}

// round 3
// speedup vs baseline: 1.6526x; 1.6526x over previous
#include <cuda_runtime.h>
#include <math.h>
#include <cstdint>

#define S_LEN    4096
#define DM       1024
#define NHEADS   16
#define HDIM     64

// Scratch (allocation-free rule: __device__ globals)
__device__ float g_Q[S_LEN * DM];
__device__ float g_K[S_LEN * DM];
__device__ float g_V[S_LEN * DM];
__device__ float g_A[S_LEN * DM];
__device__ float g_invfreq[HDIM / 2];

typedef unsigned long long ull;

// ===========================================================================
// Helpers
// ===========================================================================
__device__ __forceinline__ uint32_t smem_u32(const void* p) {
    uint32_t a;
    asm("{ .reg .u64 t; cvta.to.shared.u64 t, %1; cvt.u32.u64 %0, t; }"
        : "=r"(a) : "l"(p));
    return a;
}
__device__ __forceinline__ void cp_async16(uint32_t s, const void* g) {
    asm volatile("cp.async.cg.shared.global [%0], [%1], 16;" :: "r"(s), "l"(g));
}
#define CP_ASYNC_COMMIT()  asm volatile("cp.async.commit_group;" ::: "memory")
#define CP_ASYNC_WAIT(n)   asm volatile("cp.async.wait_group %0;" :: "n"(n) : "memory")

__device__ __forceinline__ uint32_t cvt_tf32(float f) {
    uint32_t u;
    asm("cvt.rna.tf32.f32 %0, %1;" : "=r"(u) : "f"(f));
    return u;
}
__device__ __forceinline__ void mma_tf32(float* c, const uint32_t* a, const uint32_t* b) {
    asm volatile(
        "mma.sync.aligned.m16n8k8.row.col.f32.tf32.tf32.f32 "
        "{%0,%1,%2,%3}, {%4,%5,%6,%7}, {%8,%9}, {%0,%1,%2,%3};"
        : "+f"(c[0]), "+f"(c[1]), "+f"(c[2]), "+f"(c[3])
        : "r"(a[0]), "r"(a[1]), "r"(a[2]), "r"(a[3]), "r"(b[0]), "r"(b[1]));
}

// packed f32x2 ops (Blackwell)
__device__ __forceinline__ ull pack2(float x, float y) {
    ull r; asm("mov.b64 %0, {%1, %2};" : "=l"(r) : "f"(x), "f"(y)); return r;
}
__device__ __forceinline__ void ffma2(ull& d, ull a, ull b) {
    asm("fma.rn.f32x2 %0, %1, %2, %3;" : "=l"(d) : "l"(a), "l"(b), "l"(d));
}
__device__ __forceinline__ void fmul2(ull& d, ull a, ull b) {
    asm("mul.rn.f32x2 %0, %1, %2;" : "=l"(d) : "l"(a), "l"(b));
}
__device__ __forceinline__ float2 unpack2(ull v) {
    float x, y; asm("mov.b64 {%0, %1}, %2;" : "=f"(x), "=f"(y) : "l"(v));
    return make_float2(x, y);
}

// ===========================================================================
// tf32 mma.sync GEMM (NT): C[M,N] = A[M,K] * B[N,K]^T,  M=4096, N=K=1024
// 128x128x16 tile, 256 threads (8 warps, 4x2), warp tile 32x64,
// double-buffered cp.async, stride-20 smem (conflict-free fragment loads)
// ===========================================================================
#define BM 128
#define BN 128
#define BK 16
#define KTILES (DM / BK)     // 64
#define SSTR 20              // padded row stride (floats)

__global__ __launch_bounds__(256) void gemm_mma(
    const float* __restrict__ A, const float* __restrict__ B, float* __restrict__ C)
{
    __shared__ __align__(16) float As[2][BM][SSTR];
    __shared__ __align__(16) float Bs[2][BN][SSTR];

    const int tid  = threadIdx.x;
    const int wid  = tid >> 5;
    const int lane = tid & 31;
    const int wm   = wid >> 1;        // 0..3
    const int wn   = wid & 1;         // 0..1
    const int r    = lane >> 2;       // 0..7
    const int c4   = lane & 3;        // 0..3
    const int row0 = blockIdx.y * BM;
    const int col0 = blockIdx.x * BN;

    const uint32_t as_base = smem_u32(As);
    const uint32_t bs_base = smem_u32(Bs);

    float acc[2][8][4];
#pragma unroll
    for (int mt = 0; mt < 2; mt++)
#pragma unroll
        for (int nt = 0; nt < 8; nt++)
#pragma unroll
            for (int i = 0; i < 4; i++) acc[mt][nt][i] = 0.f;

    auto load_tile = [&](int kt, int buf) {
        const int k0 = kt * BK;
#pragma unroll
        for (int i = 0; i < 2; i++) {
            int chunk = tid + i * 256;      // 0..511
            int m  = chunk >> 2;            // 0..127
            int cc = chunk & 3;             // 0..3
            uint32_t soff = (uint32_t)(((buf * BM + m) * SSTR + cc * 4) * 4);
            cp_async16(as_base + soff, A + (size_t)(row0 + m) * DM + k0 + cc * 4);
            cp_async16(bs_base + soff, B + (size_t)(col0 + m) * DM + k0 + cc * 4);
        }
        CP_ASYNC_COMMIT();
    };

    load_tile(0, 0);

    for (int kt = 0; kt < KTILES; kt++) {
        const int buf = kt & 1;
        if (kt + 1 < KTILES) {
            load_tile(kt + 1, buf ^ 1);
            CP_ASYNC_WAIT(1);
        } else {
            CP_ASYNC_WAIT(0);
        }
        __syncthreads();

#pragma unroll
        for (int s = 0; s < 2; s++) {       // two k8 steps per BK=16
            const int k = s * 8 + c4;
            uint32_t au[2][4], bu[8][2];
#pragma unroll
            for (int mt = 0; mt < 2; mt++) {
                int m = wm * 32 + mt * 16 + r;
                au[mt][0] = cvt_tf32(As[buf][m][k]);
                au[mt][1] = cvt_tf32(As[buf][m + 8][k]);
                au[mt][2] = cvt_tf32(As[buf][m][k + 4]);
                au[mt][3] = cvt_tf32(As[buf][m + 8][k + 4]);
            }
#pragma unroll
            for (int nt = 0; nt < 8; nt++) {
                int n = wn * 64 + nt * 8 + r;
                bu[nt][0] = cvt_tf32(Bs[buf][n][k]);
                bu[nt][1] = cvt_tf32(Bs[buf][n][k + 4]);
            }
#pragma unroll
            for (int mt = 0; mt < 2; mt++)
#pragma unroll
                for (int nt = 0; nt < 8; nt++)
                    mma_tf32(acc[mt][nt], au[mt], bu[nt]);
        }
        __syncthreads();
    }

#pragma unroll
    for (int mt = 0; mt < 2; mt++) {
#pragma unroll
        for (int nt = 0; nt < 8; nt++) {
            int row = row0 + wm * 32 + mt * 16 + r;
            int col = col0 + wn * 64 + nt * 8 + c4 * 2;
            *(float2*)&C[(size_t)row * DM + col] =
                make_float2(acc[mt][nt][0], acc[mt][nt][1]);
            *(float2*)&C[(size_t)(row + 8) * DM + col] =
                make_float2(acc[mt][nt][2], acc[mt][nt][3]);
        }
    }
}

// ---------------------------------------------------------------------------
// inv_freq in double precision
// ---------------------------------------------------------------------------
__global__ void freq_kernel() {
    int j = threadIdx.x;
    if (j < HDIM / 2) {
        double e = -(double)j / 32.0 * log(10000.0);
        g_invfreq[j] = (float)exp(e);
    }
}

// ---------------------------------------------------------------------------
// RoPE: interleaved (even,odd) rotation applied in-place to Q and K
// ---------------------------------------------------------------------------
__global__ __launch_bounds__(256) void rope_kernel(
    float* __restrict__ Q, float* __restrict__ Kd, const int* __restrict__ pos)
{
    int idx = blockIdx.x * blockDim.x + threadIdx.x;
    if (idx >= S_LEN * (DM / 2)) return;
    int s = idx >> 9;
    int p = idx & 511;
    int h = p >> 5;
    int j = p & 31;
    float ang = (float)pos[s] * g_invfreq[j];
    float sn, cs;
    sincosf(ang, &sn, &cs);
    size_t base = (size_t)s * DM + h * HDIM + 2 * j;
    float2 qv = *(float2*)(Q + base);
    float2 kv = *(float2*)(Kd + base);
    *(float2*)(Q + base)  = make_float2(qv.x * cs - qv.y * sn, qv.x * sn + qv.y * cs);
    *(float2*)(Kd + base) = make_float2(kv.x * cs - kv.y * sn, kv.x * sn + kv.y * cs);
}

// ---------------------------------------------------------------------------
// Causal flash attention. 1 query/thread, 128 q/CTA, 64-key tiles.
// f32x2 packed FMA, 8-wide score blocking, reversed CTA order (heavy first).
// ---------------------------------------------------------------------------
__global__ __launch_bounds__(128) void flash_attn(
    const float* __restrict__ Q, const float* __restrict__ K,
    const float* __restrict__ V, float* __restrict__ O)
{
    __shared__ __align__(16) float Ks[64][64];
    __shared__ __align__(16) float Vs[64][64];

    const int h     = blockIdx.y;
    const int qblk  = gridDim.x - 1 - blockIdx.x;   // heavy blocks first
    const int qbase = qblk * 128;
    const int tid   = threadIdx.x;
    const int s     = qbase + tid;

    ull q2[32], acc2[32];
    const float* Qp = Q + (size_t)s * DM + h * HDIM;
#pragma unroll
    for (int t = 0; t < 16; t++) {
        float4 v = *(const float4*)(Qp + 4 * t);
        q2[2 * t]     = pack2(v.x * 0.125f, v.y * 0.125f);
        q2[2 * t + 1] = pack2(v.z * 0.125f, v.w * 0.125f);
        acc2[2 * t] = 0ull;
        acc2[2 * t + 1] = 0ull;
    }

    float m = -1e30f;
    float l = 0.f;
    const float NEG_INF = __int_as_float(0xff800000);
    const int kend = qbase + 128;

    for (int kt = 0; kt < kend; kt += 64) {
        __syncthreads();
        for (int i = tid; i < 64 * 64 / 4; i += 128) {
            int rr = i >> 4;
            int cc = (i & 15) << 2;
            size_t off = (size_t)(kt + rr) * DM + h * HDIM + cc;
            *(float4*)&Ks[rr][cc] = *(const float4*)(K + off);
            *(float4*)&Vs[rr][cc] = *(const float4*)(V + off);
        }
        __syncthreads();

        int jmax = s - kt + 1;
        if (jmax > 64) jmax = 64;

        for (int jb = 0; jb < jmax; jb += 8) {
            float sc[8];
#pragma unroll
            for (int i = 0; i < 8; i++) {
                const ulonglong2* kr = (const ulonglong2*)&Ks[jb + i][0];
                ull s0 = 0, s1 = 0, s2 = 0, s3 = 0;
#pragma unroll
                for (int t = 0; t < 4; t++) {
                    ulonglong2 k0 = kr[t * 4 + 0];
                    ulonglong2 k1 = kr[t * 4 + 1];
                    ulonglong2 k2 = kr[t * 4 + 2];
                    ulonglong2 k3 = kr[t * 4 + 3];
                    ffma2(s0, q2[t * 8 + 0], k0.x); ffma2(s0, q2[t * 8 + 1], k0.y);
                    ffma2(s1, q2[t * 8 + 2], k1.x); ffma2(s1, q2[t * 8 + 3], k1.y);
                    ffma2(s2, q2[t * 8 + 4], k2.x); ffma2(s2, q2[t * 8 + 5], k2.y);
                    ffma2(s3, q2[t * 8 + 6], k3.x); ffma2(s3, q2[t * 8 + 7], k3.y);
                }
                float2 f0 = unpack2(s0), f1 = unpack2(s1);
                float2 f2 = unpack2(s2), f3 = unpack2(s3);
                float sv = ((f0.x + f0.y) + (f1.x + f1.y)) +
                           ((f2.x + f2.y) + (f3.x + f3.y));
                sc[i] = (jb + i < jmax) ? sv : NEG_INF;
            }

            float mx = sc[0];
#pragma unroll
            for (int i = 1; i < 8; i++) mx = fmaxf(mx, sc[i]);
            if (mx > m) {
                float scale = __expf(m - mx);
                m = mx;
                l *= scale;
                ull ss = pack2(scale, scale);
#pragma unroll
                for (int d = 0; d < 32; d++) fmul2(acc2[d], acc2[d], ss);
            }

#pragma unroll
            for (int i = 0; i < 8; i++) {
                float p = __expf(sc[i] - m);
                l += p;
                ull pp = pack2(p, p);
                const ulonglong2* vr = (const ulonglong2*)&Vs[jb + i][0];
#pragma unroll
                for (int t = 0; t < 16; t++) {
                    ulonglong2 v = vr[t];
                    ffma2(acc2[2 * t],     v.x, pp);
                    ffma2(acc2[2 * t + 1], v.y, pp);
                }
            }
        }
    }

    float rcp = 1.0f / l;
    float* Op = O + (size_t)s * DM + h * HDIM;
#pragma unroll
    for (int t = 0; t < 16; t++) {
        float2 a0 = unpack2(acc2[2 * t]);
        float2 a1 = unpack2(acc2[2 * t + 1]);
        *(float4*)(Op + 4 * t) = make_float4(a0.x * rcp, a0.y * rcp,
                                             a1.x * rcp, a1.y * rcp);
    }
}

// ---------------------------------------------------------------------------
// Launcher
// ---------------------------------------------------------------------------
extern "C" void kernel_launch(void* const* d_in, const int* in_sizes, int n_in,
                              void* d_out, int out_size)
{
    const float* x  = (const float*)d_in[0];
    const float* Wq = (const float*)d_in[1];
    const float* Wk = (const float*)d_in[2];
    const float* Wv = (const float*)d_in[3];
    const float* Wo = (const float*)d_in[4];
    const int*  pos = (const int*)  d_in[5];
    float* out = (float*)d_out;

    float *Qb, *Kb, *Vb, *Ab;
    cudaGetSymbolAddress((void**)&Qb, g_Q);
    cudaGetSymbolAddress((void**)&Kb, g_K);
    cudaGetSymbolAddress((void**)&Vb, g_V);
    cudaGetSymbolAddress((void**)&Ab, g_A);

    dim3 ggrid(DM / BN, S_LEN / BM);       // (8, 32)

    freq_kernel<<<1, 32>>>();
    gemm_mma<<<ggrid, 256>>>(x, Wq, Qb);
    gemm_mma<<<ggrid, 256>>>(x, Wk, Kb);
    gemm_mma<<<ggrid, 256>>>(x, Wv, Vb);

    int rope_threads = S_LEN * (DM / 2);
    rope_kernel<<<(rope_threads + 255) / 256, 256>>>(Qb, Kb, pos);

    flash_attn<<<dim3(S_LEN / 128, NHEADS), 128>>>(Qb, Kb, Vb, Ab);

    gemm_mma<<<ggrid, 256>>>(Ab, Wo, out);
}

// round 4
// speedup vs baseline: 5.2478x; 3.1756x over previous
#include <cuda_runtime.h>
#include <math.h>
#include <cstdint>
#include <cuda_fp16.h>

#define S_LEN    4096
#define DM       1024
#define NHEADS   16
#define HDIM     64

// Scratch (allocation-free rule: __device__ globals)
__device__ float g_Q[S_LEN * DM];
__device__ float g_K[S_LEN * DM];
__device__ float g_V[S_LEN * DM];
__device__ float g_A[S_LEN * DM];
__device__ float g_invfreq[HDIM / 2];

typedef unsigned long long ull;

// ===========================================================================
// Helpers
// ===========================================================================
__device__ __forceinline__ uint32_t smem_u32(const void* p) {
    uint32_t a;
    asm("{ .reg .u64 t; cvta.to.shared.u64 t, %1; cvt.u32.u64 %0, t; }"
        : "=r"(a) : "l"(p));
    return a;
}
__device__ __forceinline__ void cp_async16(uint32_t s, const void* g) {
    asm volatile("cp.async.cg.shared.global [%0], [%1], 16;" :: "r"(s), "l"(g));
}
#define CP_ASYNC_COMMIT()  asm volatile("cp.async.commit_group;" ::: "memory")
#define CP_ASYNC_WAIT(n)   asm volatile("cp.async.wait_group %0;" :: "n"(n) : "memory")

__device__ __forceinline__ uint32_t cvt_tf32(float f) {
    uint32_t u;
    asm("cvt.rna.tf32.f32 %0, %1;" : "=r"(u) : "f"(f));
    return u;
}
__device__ __forceinline__ float tf32r(float f) {
    return __uint_as_float(cvt_tf32(f));
}
__device__ __forceinline__ void mma_tf32(float* c, const uint32_t* a, const uint32_t* b) {
    asm volatile(
        "mma.sync.aligned.m16n8k8.row.col.f32.tf32.tf32.f32 "
        "{%0,%1,%2,%3}, {%4,%5,%6,%7}, {%8,%9}, {%0,%1,%2,%3};"
        : "+f"(c[0]), "+f"(c[1]), "+f"(c[2]), "+f"(c[3])
        : "r"(a[0]), "r"(a[1]), "r"(a[2]), "r"(a[3]), "r"(b[0]), "r"(b[1]));
}
__device__ __forceinline__ void mma_f16(float* c, uint32_t a0, uint32_t a1,
                                        uint32_t a2, uint32_t a3,
                                        uint32_t b0, uint32_t b1) {
    asm volatile(
        "mma.sync.aligned.m16n8k16.row.col.f32.f16.f16.f32 "
        "{%0,%1,%2,%3}, {%4,%5,%6,%7}, {%8,%9}, {%0,%1,%2,%3};"
        : "+f"(c[0]), "+f"(c[1]), "+f"(c[2]), "+f"(c[3])
        : "r"(a0), "r"(a1), "r"(a2), "r"(a3), "r"(b0), "r"(b1));
}
__device__ __forceinline__ uint32_t h2pack(float lo, float hi) {
    __half2 h = __floats2half2_rn(lo, hi);
    return *(uint32_t*)&h;
}
__device__ __forceinline__ void ldmatrix_x2_trans(uint32_t& b0, uint32_t& b1, uint32_t addr) {
    asm volatile("ldmatrix.sync.aligned.m8n8.x2.trans.shared.b16 {%0,%1}, [%2];"
                 : "=r"(b0), "=r"(b1) : "r"(addr));
}

// ===========================================================================
// tf32 mma.sync GEMM (NT): C[M,N] = A[M,K] * B[N,K]^T,  M=4096, N=K=1024
// (unchanged from R3 — 80us each, known good)
// ===========================================================================
#define BM 128
#define BN 128
#define BK 16
#define KTILES (DM / BK)     // 64
#define SSTR 20              // padded row stride (floats)

__global__ __launch_bounds__(256) void gemm_mma(
    const float* __restrict__ A, const float* __restrict__ B, float* __restrict__ C)
{
    __shared__ __align__(16) float As[2][BM][SSTR];
    __shared__ __align__(16) float Bs[2][BN][SSTR];

    const int tid  = threadIdx.x;
    const int wid  = tid >> 5;
    const int lane = tid & 31;
    const int wm   = wid >> 1;
    const int wn   = wid & 1;
    const int r    = lane >> 2;
    const int c4   = lane & 3;
    const int row0 = blockIdx.y * BM;
    const int col0 = blockIdx.x * BN;

    const uint32_t as_base = smem_u32(As);
    const uint32_t bs_base = smem_u32(Bs);

    float acc[2][8][4];
#pragma unroll
    for (int mt = 0; mt < 2; mt++)
#pragma unroll
        for (int nt = 0; nt < 8; nt++)
#pragma unroll
            for (int i = 0; i < 4; i++) acc[mt][nt][i] = 0.f;

    auto load_tile = [&](int kt, int buf) {
        const int k0 = kt * BK;
#pragma unroll
        for (int i = 0; i < 2; i++) {
            int chunk = tid + i * 256;
            int m  = chunk >> 2;
            int cc = chunk & 3;
            uint32_t soff = (uint32_t)(((buf * BM + m) * SSTR + cc * 4) * 4);
            cp_async16(as_base + soff, A + (size_t)(row0 + m) * DM + k0 + cc * 4);
            cp_async16(bs_base + soff, B + (size_t)(col0 + m) * DM + k0 + cc * 4);
        }
        CP_ASYNC_COMMIT();
    };

    load_tile(0, 0);

    for (int kt = 0; kt < KTILES; kt++) {
        const int buf = kt & 1;
        if (kt + 1 < KTILES) {
            load_tile(kt + 1, buf ^ 1);
            CP_ASYNC_WAIT(1);
        } else {
            CP_ASYNC_WAIT(0);
        }
        __syncthreads();

#pragma unroll
        for (int s = 0; s < 2; s++) {
            const int k = s * 8 + c4;
            uint32_t au[2][4], bu[8][2];
#pragma unroll
            for (int mt = 0; mt < 2; mt++) {
                int m = wm * 32 + mt * 16 + r;
                au[mt][0] = cvt_tf32(As[buf][m][k]);
                au[mt][1] = cvt_tf32(As[buf][m + 8][k]);
                au[mt][2] = cvt_tf32(As[buf][m][k + 4]);
                au[mt][3] = cvt_tf32(As[buf][m + 8][k + 4]);
            }
#pragma unroll
            for (int nt = 0; nt < 8; nt++) {
                int n = wn * 64 + nt * 8 + r;
                bu[nt][0] = cvt_tf32(Bs[buf][n][k]);
                bu[nt][1] = cvt_tf32(Bs[buf][n][k + 4]);
            }
#pragma unroll
            for (int mt = 0; mt < 2; mt++)
#pragma unroll
                for (int nt = 0; nt < 8; nt++)
                    mma_tf32(acc[mt][nt], au[mt], bu[nt]);
        }
        __syncthreads();
    }

#pragma unroll
    for (int mt = 0; mt < 2; mt++) {
#pragma unroll
        for (int nt = 0; nt < 8; nt++) {
            int row = row0 + wm * 32 + mt * 16 + r;
            int col = col0 + wn * 64 + nt * 8 + c4 * 2;
            *(float2*)&C[(size_t)row * DM + col] =
                make_float2(acc[mt][nt][0], acc[mt][nt][1]);
            *(float2*)&C[(size_t)(row + 8) * DM + col] =
                make_float2(acc[mt][nt][2], acc[mt][nt][3]);
        }
    }
}

// ---------------------------------------------------------------------------
// inv_freq in double precision
// ---------------------------------------------------------------------------
__global__ void freq_kernel() {
    int j = threadIdx.x;
    if (j < HDIM / 2) {
        double e = -(double)j / 32.0 * log(10000.0);
        g_invfreq[j] = (float)exp(e);
    }
}

// ---------------------------------------------------------------------------
// RoPE: interleaved (even,odd) rotation applied in-place to Q and K
// ---------------------------------------------------------------------------
__global__ __launch_bounds__(256) void rope_kernel(
    float* __restrict__ Q, float* __restrict__ Kd, const int* __restrict__ pos)
{
    int idx = blockIdx.x * blockDim.x + threadIdx.x;
    if (idx >= S_LEN * (DM / 2)) return;
    int s = idx >> 9;
    int p = idx & 511;
    int h = p >> 5;
    int j = p & 31;
    float ang = (float)pos[s] * g_invfreq[j];
    float sn, cs;
    sincosf(ang, &sn, &cs);
    size_t base = (size_t)s * DM + h * HDIM + 2 * j;
    float2 qv = *(float2*)(Q + base);
    float2 kv = *(float2*)(Kd + base);
    *(float2*)(Q + base)  = make_float2(qv.x * cs - qv.y * sn, qv.x * sn + qv.y * cs);
    *(float2*)(Kd + base) = make_float2(kv.x * cs - kv.y * sn, kv.x * sn + kv.y * cs);
}

// ===========================================================================
// Tensor-core causal flash attention (FA2 style).
// 4 warps / CTA, 64 queries x 1 head per CTA, Bc=64 key tiles.
// S via m16n8k8.tf32; softmax in C-frags; O += P.V via m16n8k16.f16
// with P packed C->A in registers and V fetched via ldmatrix.trans.
// ===========================================================================
#define FKSTR 68     // Ks row stride (floats)
#define FVSTR 72     // Vs row stride (halves)

__global__ __launch_bounds__(128) void flash_mma(
    const float* __restrict__ Q, const float* __restrict__ K,
    const float* __restrict__ V, float* __restrict__ O)
{
    __shared__ __align__(16) float  Ks[64][FKSTR];
    __shared__ __align__(16) __half Vs[64][FVSTR];

    const int tid  = threadIdx.x;
    const int warp = tid >> 5;
    const int lane = tid & 31;
    const int r    = lane >> 2;
    const int c    = lane & 3;
    const int qblk = (gridDim.x >> 4) - 1 - (int)(blockIdx.x >> 4);  // heavy first
    const int h    = blockIdx.x & 15;
    const int qbase = qblk * 64;
    const int w16   = warp * 16;
    const uint32_t vs_base = smem_u32(Vs);

    // ---- stage Q (scaled by 1/8, tf32-rounded) through Ks, build A frags ---
    for (int i = 0; i < 8; i++) {
        int chunk = tid + i * 128;
        int row = chunk >> 4, c4 = (chunk & 15) * 4;
        float4 v = *(const float4*)(Q + (size_t)(qbase + row) * DM + h * HDIM + c4);
        float4 o = make_float4(tf32r(v.x * 0.125f), tf32r(v.y * 0.125f),
                               tf32r(v.z * 0.125f), tf32r(v.w * 0.125f));
        *(float4*)&Ks[row][c4] = o;
    }
    __syncthreads();

    uint32_t qa[8][4];
#pragma unroll
    for (int ks = 0; ks < 8; ks++) {
        qa[ks][0] = __float_as_uint(Ks[w16 + r][ks * 8 + c]);
        qa[ks][1] = __float_as_uint(Ks[w16 + r + 8][ks * 8 + c]);
        qa[ks][2] = __float_as_uint(Ks[w16 + r][ks * 8 + c + 4]);
        qa[ks][3] = __float_as_uint(Ks[w16 + r + 8][ks * 8 + c + 4]);
    }

    float acc[8][4];
#pragma unroll
    for (int nt = 0; nt < 8; nt++)
#pragma unroll
        for (int i = 0; i < 4; i++) acc[nt][i] = 0.f;
    float m0 = -1e30f, m1 = -1e30f, l0 = 0.f, l1 = 0.f;

    for (int kt = 0; kt <= qbase; kt += 64) {
        __syncthreads();
        // load K tile (tf32-rounded) and V tile (fp16)
        for (int i = 0; i < 8; i++) {
            int chunk = tid + i * 128;
            int row = chunk >> 4, c4 = (chunk & 15) * 4;
            size_t goff = (size_t)(kt + row) * DM + h * HDIM + c4;
            float4 kv = *(const float4*)(K + goff);
            *(float4*)&Ks[row][c4] = make_float4(tf32r(kv.x), tf32r(kv.y),
                                                 tf32r(kv.z), tf32r(kv.w));
            float4 vv = *(const float4*)(V + goff);
            __half2 p0 = __floats2half2_rn(vv.x, vv.y);
            __half2 p1 = __floats2half2_rn(vv.z, vv.w);
            *(__half2*)&Vs[row][c4]     = p0;
            *(__half2*)&Vs[row][c4 + 2] = p1;
        }
        __syncthreads();

        // ---- S = Q K^T ----------------------------------------------------
        float sc[8][4];
#pragma unroll
        for (int nt = 0; nt < 8; nt++) {
            sc[nt][0] = sc[nt][1] = sc[nt][2] = sc[nt][3] = 0.f;
            const int key = nt * 8 + r;
#pragma unroll
            for (int ks = 0; ks < 8; ks++) {
                uint32_t b[2];
                b[0] = __float_as_uint(Ks[key][ks * 8 + c]);
                b[1] = __float_as_uint(Ks[key][ks * 8 + c + 4]);
                mma_tf32(sc[nt], qa[ks], b);
            }
        }

        // ---- causal mask on the diagonal tile ------------------------------
        if (kt == qbase) {
            const int qr0 = w16 + r, qr1 = qr0 + 8;
#pragma unroll
            for (int nt = 0; nt < 8; nt++) {
                int cb = nt * 8 + 2 * c;
                if (cb     > qr0) sc[nt][0] = -1e30f;
                if (cb + 1 > qr0) sc[nt][1] = -1e30f;
                if (cb     > qr1) sc[nt][2] = -1e30f;
                if (cb + 1 > qr1) sc[nt][3] = -1e30f;
            }
        }

        // ---- online softmax ------------------------------------------------
        float mx0 = -1e30f, mx1 = -1e30f;
#pragma unroll
        for (int nt = 0; nt < 8; nt++) {
            mx0 = fmaxf(mx0, fmaxf(sc[nt][0], sc[nt][1]));
            mx1 = fmaxf(mx1, fmaxf(sc[nt][2], sc[nt][3]));
        }
        mx0 = fmaxf(mx0, __shfl_xor_sync(0xffffffffu, mx0, 1));
        mx0 = fmaxf(mx0, __shfl_xor_sync(0xffffffffu, mx0, 2));
        mx1 = fmaxf(mx1, __shfl_xor_sync(0xffffffffu, mx1, 1));
        mx1 = fmaxf(mx1, __shfl_xor_sync(0xffffffffu, mx1, 2));

        float nm0 = fmaxf(m0, mx0), nm1 = fmaxf(m1, mx1);
        float s0 = __expf(m0 - nm0), s1 = __expf(m1 - nm1);
        m0 = nm0; m1 = nm1;

        float rs0 = 0.f, rs1 = 0.f;
#pragma unroll
        for (int nt = 0; nt < 8; nt++) {
            sc[nt][0] = __expf(sc[nt][0] - nm0);
            sc[nt][1] = __expf(sc[nt][1] - nm0);
            sc[nt][2] = __expf(sc[nt][2] - nm1);
            sc[nt][3] = __expf(sc[nt][3] - nm1);
            rs0 += sc[nt][0] + sc[nt][1];
            rs1 += sc[nt][2] + sc[nt][3];
        }
        rs0 += __shfl_xor_sync(0xffffffffu, rs0, 1);
        rs0 += __shfl_xor_sync(0xffffffffu, rs0, 2);
        rs1 += __shfl_xor_sync(0xffffffffu, rs1, 1);
        rs1 += __shfl_xor_sync(0xffffffffu, rs1, 2);
        l0 = l0 * s0 + rs0;
        l1 = l1 * s1 + rs1;

#pragma unroll
        for (int nt = 0; nt < 8; nt++) {
            acc[nt][0] *= s0; acc[nt][1] *= s0;
            acc[nt][2] *= s1; acc[nt][3] *= s1;
        }

        // ---- O += P.V  (P packed to fp16 A-frags; V via ldmatrix.trans) ----
#pragma unroll
        for (int kk = 0; kk < 4; kk++) {
            uint32_t a0 = h2pack(sc[2 * kk][0],     sc[2 * kk][1]);
            uint32_t a1 = h2pack(sc[2 * kk][2],     sc[2 * kk][3]);
            uint32_t a2 = h2pack(sc[2 * kk + 1][0], sc[2 * kk + 1][1]);
            uint32_t a3 = h2pack(sc[2 * kk + 1][2], sc[2 * kk + 1][3]);
            const int lrow = kk * 16 + (lane & 15);
#pragma unroll
            for (int nd = 0; nd < 8; nd++) {
                uint32_t baddr = vs_base +
                    (uint32_t)((lrow * FVSTR + nd * 8) * 2);
                uint32_t b0, b1;
                ldmatrix_x2_trans(b0, b1, baddr);
                mma_f16(acc[nd], a0, a1, a2, a3, b0, b1);
            }
        }
    }

    // ---- epilogue ---------------------------------------------------------
    float i0 = 1.f / l0, i1 = 1.f / l1;
    const int row0 = qbase + w16 + r;
#pragma unroll
    for (int nt = 0; nt < 8; nt++) {
        int col = h * HDIM + nt * 8 + 2 * c;
        *(float2*)&O[(size_t)row0 * DM + col] =
            make_float2(acc[nt][0] * i0, acc[nt][1] * i0);
        *(float2*)&O[(size_t)(row0 + 8) * DM + col] =
            make_float2(acc[nt][2] * i1, acc[nt][3] * i1);
    }
}

// ---------------------------------------------------------------------------
// Launcher
// ---------------------------------------------------------------------------
extern "C" void kernel_launch(void* const* d_in, const int* in_sizes, int n_in,
                              void* d_out, int out_size)
{
    const float* x  = (const float*)d_in[0];
    const float* Wq = (const float*)d_in[1];
    const float* Wk = (const float*)d_in[2];
    const float* Wv = (const float*)d_in[3];
    const float* Wo = (const float*)d_in[4];
    const int*  pos = (const int*)  d_in[5];
    float* out = (float*)d_out;

    float *Qb, *Kb, *Vb, *Ab;
    cudaGetSymbolAddress((void**)&Qb, g_Q);
    cudaGetSymbolAddress((void**)&Kb, g_K);
    cudaGetSymbolAddress((void**)&Vb, g_V);
    cudaGetSymbolAddress((void**)&Ab, g_A);

    dim3 ggrid(DM / BN, S_LEN / BM);       // (8, 32)

    freq_kernel<<<1, 32>>>();
    gemm_mma<<<ggrid, 256>>>(x, Wq, Qb);
    gemm_mma<<<ggrid, 256>>>(x, Wk, Kb);
    gemm_mma<<<ggrid, 256>>>(x, Wv, Vb);

    int rope_threads = S_LEN * (DM / 2);
    rope_kernel<<<(rope_threads + 255) / 256, 256>>>(Qb, Kb, pos);

    flash_mma<<<(S_LEN / 64) * NHEADS, 128>>>(Qb, Kb, Vb, Ab);

    gemm_mma<<<ggrid, 256>>>(Ab, Wo, out);
}

// round 5
// speedup vs baseline: 5.4011x; 1.0292x over previous
#include <cuda_runtime.h>
#include <math.h>
#include <cstdint>
#include <cuda_fp16.h>

#define S_LEN    4096
#define DM       1024
#define NHEADS   16
#define HDIM     64

// Scratch (allocation-free rule: __device__ globals)
__device__ float  g_X[S_LEN * DM];        // tf32-rounded x
__device__ float  g_W[4 * DM * DM];       // tf32-rounded Wq,Wk,Wv,Wo
__device__ float  g_Q[S_LEN * DM];
__device__ float  g_K[S_LEN * DM];
__device__ __half g_Vh[S_LEN * DM];
__device__ float  g_A[S_LEN * DM];        // tf32-rounded attn output
__device__ float  g_invfreq[HDIM / 2];

// ===========================================================================
// Helpers
// ===========================================================================
__device__ __forceinline__ uint32_t smem_u32(const void* p) {
    uint32_t a;
    asm("{ .reg .u64 t; cvta.to.shared.u64 t, %1; cvt.u32.u64 %0, t; }"
        : "=r"(a) : "l"(p));
    return a;
}
__device__ __forceinline__ void cp_async16(uint32_t s, const void* g) {
    asm volatile("cp.async.cg.shared.global [%0], [%1], 16;" :: "r"(s), "l"(g));
}
#define CP_ASYNC_COMMIT()  asm volatile("cp.async.commit_group;" ::: "memory")
#define CP_ASYNC_WAIT(n)   asm volatile("cp.async.wait_group %0;" :: "n"(n) : "memory")

__device__ __forceinline__ uint32_t cvt_tf32(float f) {
    uint32_t u;
    asm("cvt.rna.tf32.f32 %0, %1;" : "=r"(u) : "f"(f));
    return u;
}
__device__ __forceinline__ float tf32r(float f) {
    return __uint_as_float(cvt_tf32(f));
}
__device__ __forceinline__ void mma_tf32(float* c, const uint32_t* a, const uint32_t* b) {
    asm volatile(
        "mma.sync.aligned.m16n8k8.row.col.f32.tf32.tf32.f32 "
        "{%0,%1,%2,%3}, {%4,%5,%6,%7}, {%8,%9}, {%0,%1,%2,%3};"
        : "+f"(c[0]), "+f"(c[1]), "+f"(c[2]), "+f"(c[3])
        : "r"(a[0]), "r"(a[1]), "r"(a[2]), "r"(a[3]), "r"(b[0]), "r"(b[1]));
}
__device__ __forceinline__ void mma_f16(float* c, uint32_t a0, uint32_t a1,
                                        uint32_t a2, uint32_t a3,
                                        uint32_t b0, uint32_t b1) {
    asm volatile(
        "mma.sync.aligned.m16n8k16.row.col.f32.f16.f16.f32 "
        "{%0,%1,%2,%3}, {%4,%5,%6,%7}, {%8,%9}, {%0,%1,%2,%3};"
        : "+f"(c[0]), "+f"(c[1]), "+f"(c[2]), "+f"(c[3])
        : "r"(a0), "r"(a1), "r"(a2), "r"(a3), "r"(b0), "r"(b1));
}
__device__ __forceinline__ uint32_t h2pack(float lo, float hi) {
    __half2 h = __floats2half2_rn(lo, hi);
    return *(uint32_t*)&h;
}
__device__ __forceinline__ void ldmatrix_x2_trans(uint32_t& b0, uint32_t& b1, uint32_t addr) {
    asm volatile("ldmatrix.sync.aligned.m8n8.x2.trans.shared.b16 {%0,%1}, [%2];"
                 : "=r"(b0), "=r"(b1) : "r"(addr));
}

// ===========================================================================
// tf32 pre-rounding pass (hoists cvt out of GEMM inner loops)
// ===========================================================================
__global__ __launch_bounds__(256) void round_tf32_kernel(
    float4* __restrict__ dst, const float4* __restrict__ src, int n4)
{
    int i = blockIdx.x * blockDim.x + threadIdx.x;
    if (i >= n4) return;
    float4 v = src[i];
    dst[i] = make_float4(tf32r(v.x), tf32r(v.y), tf32r(v.z), tf32r(v.w));
}

// ===========================================================================
// tf32 mma.sync GEMM (NT): C[M,N] = A[M,K] * B[N,K]^T, inputs pre-rounded.
// 128x256x16 tile, 256 threads (8 warps 2x4), warp tile 64x64,
// single-sync cp.async double buffer. Grid 4x32 = 128 CTAs = one wave.
// ===========================================================================
#define GBM 128
#define GBN 256
#define GBK 16
#define GKT (DM / GBK)                // 64
#define GSSTR 20
#define GEMM_ASZ (GBM * GSSTR)        // floats per A stage
#define GEMM_BSZ (GBN * GSSTR)
#define GEMM_SMEM ((2 * GEMM_ASZ + 2 * GEMM_BSZ) * 4)   // 61440 B

template <typename OutT>
__global__ __launch_bounds__(256) void gemm_mma(
    const float* __restrict__ A, const float* __restrict__ B, OutT* __restrict__ C)
{
    extern __shared__ __align__(16) float smf[];
    float* As = smf;
    float* Bs = smf + 2 * GEMM_ASZ;
    const uint32_t as_u = smem_u32(As);
    const uint32_t bs_u = smem_u32(Bs);

    const int tid  = threadIdx.x;
    const int wid  = tid >> 5;
    const int lane = tid & 31;
    const int wm   = wid >> 2;        // 0..1
    const int wn   = wid & 3;         // 0..3
    const int r    = lane >> 2;
    const int c4   = lane & 3;
    const int row0 = blockIdx.y * GBM;
    const int col0 = blockIdx.x * GBN;

    float acc[4][8][4];
#pragma unroll
    for (int mt = 0; mt < 4; mt++)
#pragma unroll
        for (int nt = 0; nt < 8; nt++)
#pragma unroll
            for (int i = 0; i < 4; i++) acc[mt][nt][i] = 0.f;

    auto load_tile = [&](int kt, int buf) {
        const int k0 = kt * GBK;
#pragma unroll
        for (int i = 0; i < 2; i++) {                 // A: 512 chunks
            int chunk = tid + i * 256;
            int m  = chunk >> 2, cc = (chunk & 3) * 4;
            cp_async16(as_u + (uint32_t)((buf * GEMM_ASZ + m * GSSTR + cc) * 4),
                       A + (size_t)(row0 + m) * DM + k0 + cc);
        }
#pragma unroll
        for (int i = 0; i < 4; i++) {                 // B: 1024 chunks
            int chunk = tid + i * 256;
            int m  = chunk >> 2, cc = (chunk & 3) * 4;
            cp_async16(bs_u + (uint32_t)((buf * GEMM_BSZ + m * GSSTR + cc) * 4),
                       B + (size_t)(col0 + m) * DM + k0 + cc);
        }
        CP_ASYNC_COMMIT();
    };

    load_tile(0, 0);

    for (int kt = 0; kt < GKT; kt++) {
        const int buf = kt & 1;
        CP_ASYNC_WAIT(0);
        __syncthreads();
        if (kt + 1 < GKT) load_tile(kt + 1, buf ^ 1);

        const float* Ab = As + buf * GEMM_ASZ;
        const float* Bb = Bs + buf * GEMM_BSZ;
#pragma unroll
        for (int s = 0; s < 2; s++) {
            const int k = s * 8 + c4;
            uint32_t au[4][4], bu[8][2];
#pragma unroll
            for (int mt = 0; mt < 4; mt++) {
                int m = wm * 64 + mt * 16 + r;
                au[mt][0] = __float_as_uint(Ab[m * GSSTR + k]);
                au[mt][1] = __float_as_uint(Ab[(m + 8) * GSSTR + k]);
                au[mt][2] = __float_as_uint(Ab[m * GSSTR + k + 4]);
                au[mt][3] = __float_as_uint(Ab[(m + 8) * GSSTR + k + 4]);
            }
#pragma unroll
            for (int nt = 0; nt < 8; nt++) {
                int n = wn * 64 + nt * 8 + r;
                bu[nt][0] = __float_as_uint(Bb[n * GSSTR + k]);
                bu[nt][1] = __float_as_uint(Bb[n * GSSTR + k + 4]);
            }
#pragma unroll
            for (int mt = 0; mt < 4; mt++)
#pragma unroll
                for (int nt = 0; nt < 8; nt++)
                    mma_tf32(acc[mt][nt], au[mt], bu[nt]);
        }
    }

#pragma unroll
    for (int mt = 0; mt < 4; mt++) {
#pragma unroll
        for (int nt = 0; nt < 8; nt++) {
            int row = row0 + wm * 64 + mt * 16 + r;
            int col = col0 + wn * 64 + nt * 8 + c4 * 2;
            if (sizeof(OutT) == 4) {
                *(float2*)((float*)C + (size_t)row * DM + col) =
                    make_float2(acc[mt][nt][0], acc[mt][nt][1]);
                *(float2*)((float*)C + (size_t)(row + 8) * DM + col) =
                    make_float2(acc[mt][nt][2], acc[mt][nt][3]);
            } else {
                *(__half2*)((__half*)C + (size_t)row * DM + col) =
                    __floats2half2_rn(acc[mt][nt][0], acc[mt][nt][1]);
                *(__half2*)((__half*)C + (size_t)(row + 8) * DM + col) =
                    __floats2half2_rn(acc[mt][nt][2], acc[mt][nt][3]);
            }
        }
    }
}

// ---------------------------------------------------------------------------
// inv_freq in double precision
// ---------------------------------------------------------------------------
__global__ void freq_kernel() {
    int j = threadIdx.x;
    if (j < HDIM / 2) {
        double e = -(double)j / 32.0 * log(10000.0);
        g_invfreq[j] = (float)exp(e);
    }
}

// ---------------------------------------------------------------------------
// RoPE in-place; writes tf32-rounded K and tf32-rounded, 1/8-prescaled Q.
// ---------------------------------------------------------------------------
__global__ __launch_bounds__(256) void rope_kernel(
    float* __restrict__ Q, float* __restrict__ Kd, const int* __restrict__ pos)
{
    int idx = blockIdx.x * blockDim.x + threadIdx.x;
    if (idx >= S_LEN * (DM / 2)) return;
    int s = idx >> 9;
    int p = idx & 511;
    int h = p >> 5;
    int j = p & 31;
    float ang = (float)pos[s] * g_invfreq[j];
    float sn, cs;
    sincosf(ang, &sn, &cs);
    size_t base = (size_t)s * DM + h * HDIM + 2 * j;
    float2 qv = *(float2*)(Q + base);
    float2 kv = *(float2*)(Kd + base);
    *(float2*)(Q + base) = make_float2(
        tf32r(0.125f * (qv.x * cs - qv.y * sn)),
        tf32r(0.125f * (qv.x * sn + qv.y * cs)));
    *(float2*)(Kd + base) = make_float2(
        tf32r(kv.x * cs - kv.y * sn),
        tf32r(kv.x * sn + kv.y * cs));
}

// ===========================================================================
// Tensor-core causal flash attention, double-buffered cp.async K/V loads.
// K pre-rounded tf32 fp32, V pre-converted fp16 — loader is raw bytes.
// ===========================================================================
#define FKSTR 68                     // K row stride (floats)
#define FVSTR 72                     // V row stride (halves)
#define FK_SZ (64 * FKSTR)           // floats per stage
#define FV_SZ (64 * FVSTR)           // halves per stage
#define FLASH_SMEM (2 * FK_SZ * 4 + 2 * FV_SZ * 2)   // 53248 B

__global__ __launch_bounds__(128) void flash_mma(
    const float* __restrict__ Q, const float* __restrict__ K,
    const __half* __restrict__ V, float* __restrict__ O)
{
    extern __shared__ __align__(16) char fsm[];
    float*  Ksm = (float*)fsm;
    __half* Vsm = (__half*)(fsm + 2 * FK_SZ * 4);
    const uint32_t ks_u = smem_u32(Ksm);
    const uint32_t vs_u = smem_u32(Vsm);

    const int tid  = threadIdx.x;
    const int warp = tid >> 5;
    const int lane = tid & 31;
    const int r    = lane >> 2;
    const int c    = lane & 3;
    const int qblk = (gridDim.x >> 4) - 1 - (int)(blockIdx.x >> 4);  // heavy first
    const int h    = blockIdx.x & 15;
    const int qbase = qblk * 64;
    const int w16   = warp * 16;

    // ---- stage Q (already tf32-rounded & 1/8-scaled) through Ksm buf0 -----
    for (int i = 0; i < 8; i++) {
        int chunk = tid + i * 128;
        int row = chunk >> 4, c4 = (chunk & 15) * 4;
        *(float4*)&Ksm[row * FKSTR + c4] =
            *(const float4*)(Q + (size_t)(qbase + row) * DM + h * HDIM + c4);
    }
    __syncthreads();

    uint32_t qa[8][4];
#pragma unroll
    for (int ks = 0; ks < 8; ks++) {
        qa[ks][0] = __float_as_uint(Ksm[(w16 + r) * FKSTR + ks * 8 + c]);
        qa[ks][1] = __float_as_uint(Ksm[(w16 + r + 8) * FKSTR + ks * 8 + c]);
        qa[ks][2] = __float_as_uint(Ksm[(w16 + r) * FKSTR + ks * 8 + c + 4]);
        qa[ks][3] = __float_as_uint(Ksm[(w16 + r + 8) * FKSTR + ks * 8 + c + 4]);
    }
    __syncthreads();

    auto load_tile = [&](int buf, int kt) {
#pragma unroll
        for (int i = 0; i < 8; i++) {                 // K: 1024 chunks
            int chunk = tid + i * 128;
            int row = chunk >> 4, cc = (chunk & 15) * 4;
            cp_async16(ks_u + (uint32_t)((buf * FK_SZ + row * FKSTR + cc) * 4),
                       K + (size_t)(kt + row) * DM + h * HDIM + cc);
        }
#pragma unroll
        for (int i = 0; i < 4; i++) {                 // V: 512 chunks
            int chunk = tid + i * 128;
            int row = chunk >> 3, cc = (chunk & 7) * 8;
            cp_async16(vs_u + (uint32_t)((buf * FV_SZ + row * FVSTR + cc) * 2),
                       V + (size_t)(kt + row) * DM + h * HDIM + cc);
        }
        CP_ASYNC_COMMIT();
    };

    float acc[8][4];
#pragma unroll
    for (int nt = 0; nt < 8; nt++)
#pragma unroll
        for (int i = 0; i < 4; i++) acc[nt][i] = 0.f;
    float m0 = -1e30f, m1 = -1e30f, l0 = 0.f, l1 = 0.f;

    load_tile(0, 0);

    for (int kt = 0; kt <= qbase; kt += 64) {
        const int buf = (kt >> 6) & 1;
        CP_ASYNC_WAIT(0);
        __syncthreads();
        if (kt + 64 <= qbase) load_tile(buf ^ 1, kt + 64);

        const float* Kb = Ksm + buf * FK_SZ;
        const uint32_t vb_u = vs_u + (uint32_t)(buf * FV_SZ * 2);

        // ---- S = Q K^T ----------------------------------------------------
        float sc[8][4];
#pragma unroll
        for (int nt = 0; nt < 8; nt++) {
            sc[nt][0] = sc[nt][1] = sc[nt][2] = sc[nt][3] = 0.f;
            const int key = nt * 8 + r;
#pragma unroll
            for (int ks = 0; ks < 8; ks++) {
                uint32_t b[2];
                b[0] = __float_as_uint(Kb[key * FKSTR + ks * 8 + c]);
                b[1] = __float_as_uint(Kb[key * FKSTR + ks * 8 + c + 4]);
                mma_tf32(sc[nt], qa[ks], b);
            }
        }

        // ---- causal mask on the diagonal tile ------------------------------
        if (kt == qbase) {
            const int qr0 = w16 + r, qr1 = qr0 + 8;
#pragma unroll
            for (int nt = 0; nt < 8; nt++) {
                int cb = nt * 8 + 2 * c;
                if (cb     > qr0) sc[nt][0] = -1e30f;
                if (cb + 1 > qr0) sc[nt][1] = -1e30f;
                if (cb     > qr1) sc[nt][2] = -1e30f;
                if (cb + 1 > qr1) sc[nt][3] = -1e30f;
            }
        }

        // ---- online softmax ------------------------------------------------
        float mx0 = -1e30f, mx1 = -1e30f;
#pragma unroll
        for (int nt = 0; nt < 8; nt++) {
            mx0 = fmaxf(mx0, fmaxf(sc[nt][0], sc[nt][1]));
            mx1 = fmaxf(mx1, fmaxf(sc[nt][2], sc[nt][3]));
        }
        mx0 = fmaxf(mx0, __shfl_xor_sync(0xffffffffu, mx0, 1));
        mx0 = fmaxf(mx0, __shfl_xor_sync(0xffffffffu, mx0, 2));
        mx1 = fmaxf(mx1, __shfl_xor_sync(0xffffffffu, mx1, 1));
        mx1 = fmaxf(mx1, __shfl_xor_sync(0xffffffffu, mx1, 2));

        float nm0 = fmaxf(m0, mx0), nm1 = fmaxf(m1, mx1);
        float s0 = __expf(m0 - nm0), s1 = __expf(m1 - nm1);
        m0 = nm0; m1 = nm1;

        float rs0 = 0.f, rs1 = 0.f;
#pragma unroll
        for (int nt = 0; nt < 8; nt++) {
            sc[nt][0] = __expf(sc[nt][0] - nm0);
            sc[nt][1] = __expf(sc[nt][1] - nm0);
            sc[nt][2] = __expf(sc[nt][2] - nm1);
            sc[nt][3] = __expf(sc[nt][3] - nm1);
            rs0 += sc[nt][0] + sc[nt][1];
            rs1 += sc[nt][2] + sc[nt][3];
        }
        rs0 += __shfl_xor_sync(0xffffffffu, rs0, 1);
        rs0 += __shfl_xor_sync(0xffffffffu, rs0, 2);
        rs1 += __shfl_xor_sync(0xffffffffu, rs1, 1);
        rs1 += __shfl_xor_sync(0xffffffffu, rs1, 2);
        l0 = l0 * s0 + rs0;
        l1 = l1 * s1 + rs1;

#pragma unroll
        for (int nt = 0; nt < 8; nt++) {
            acc[nt][0] *= s0; acc[nt][1] *= s0;
            acc[nt][2] *= s1; acc[nt][3] *= s1;
        }

        // ---- O += P.V  (P packed to fp16 A-frags; V via ldmatrix.trans) ----
#pragma unroll
        for (int kk = 0; kk < 4; kk++) {
            uint32_t a0 = h2pack(sc[2 * kk][0],     sc[2 * kk][1]);
            uint32_t a1 = h2pack(sc[2 * kk][2],     sc[2 * kk][3]);
            uint32_t a2 = h2pack(sc[2 * kk + 1][0], sc[2 * kk + 1][1]);
            uint32_t a3 = h2pack(sc[2 * kk + 1][2], sc[2 * kk + 1][3]);
            const int lrow = kk * 16 + (lane & 15);
#pragma unroll
            for (int nd = 0; nd < 8; nd++) {
                uint32_t baddr = vb_u + (uint32_t)((lrow * FVSTR + nd * 8) * 2);
                uint32_t b0, b1;
                ldmatrix_x2_trans(b0, b1, baddr);
                mma_f16(acc[nd], a0, a1, a2, a3, b0, b1);
            }
        }
        __syncthreads();
    }

    // ---- epilogue: tf32-round for the out-proj GEMM -----------------------
    float i0 = 1.f / l0, i1 = 1.f / l1;
    const int row0 = qbase + w16 + r;
#pragma unroll
    for (int nt = 0; nt < 8; nt++) {
        int col = h * HDIM + nt * 8 + 2 * c;
        *(float2*)&O[(size_t)row0 * DM + col] =
            make_float2(tf32r(acc[nt][0] * i0), tf32r(acc[nt][1] * i0));
        *(float2*)&O[(size_t)(row0 + 8) * DM + col] =
            make_float2(tf32r(acc[nt][2] * i1), tf32r(acc[nt][3] * i1));
    }
}

// ---------------------------------------------------------------------------
// Launcher
// ---------------------------------------------------------------------------
extern "C" void kernel_launch(void* const* d_in, const int* in_sizes, int n_in,
                              void* d_out, int out_size)
{
    const float* x  = (const float*)d_in[0];
    const float* Wq = (const float*)d_in[1];
    const float* Wk = (const float*)d_in[2];
    const float* Wv = (const float*)d_in[3];
    const float* Wo = (const float*)d_in[4];
    const int*  pos = (const int*)  d_in[5];
    float* out = (float*)d_out;

    float *Xr, *Wr, *Qb, *Kb, *Ab;
    __half* Vh;
    cudaGetSymbolAddress((void**)&Xr, g_X);
    cudaGetSymbolAddress((void**)&Wr, g_W);
    cudaGetSymbolAddress((void**)&Qb, g_Q);
    cudaGetSymbolAddress((void**)&Kb, g_K);
    cudaGetSymbolAddress((void**)&Vh, g_Vh);
    cudaGetSymbolAddress((void**)&Ab, g_A);

    cudaFuncSetAttribute(gemm_mma<float>,
                         cudaFuncAttributeMaxDynamicSharedMemorySize, GEMM_SMEM);
    cudaFuncSetAttribute(gemm_mma<__half>,
                         cudaFuncAttributeMaxDynamicSharedMemorySize, GEMM_SMEM);
    cudaFuncSetAttribute(flash_mma,
                         cudaFuncAttributeMaxDynamicSharedMemorySize, FLASH_SMEM);

    const int nx4 = S_LEN * DM / 4;           // 1M float4
    const int nw4 = DM * DM / 4;              // 256K float4
    round_tf32_kernel<<<(nx4 + 255) / 256, 256>>>((float4*)Xr, (const float4*)x, nx4);
    round_tf32_kernel<<<(nw4 + 255) / 256, 256>>>((float4*)(Wr + 0 * DM * DM), (const float4*)Wq, nw4);
    round_tf32_kernel<<<(nw4 + 255) / 256, 256>>>((float4*)(Wr + 1 * DM * DM), (const float4*)Wk, nw4);
    round_tf32_kernel<<<(nw4 + 255) / 256, 256>>>((float4*)(Wr + 2 * DM * DM), (const float4*)Wv, nw4);
    round_tf32_kernel<<<(nw4 + 255) / 256, 256>>>((float4*)(Wr + 3 * DM * DM), (const float4*)Wo, nw4);
    freq_kernel<<<1, 32>>>();

    dim3 ggrid(DM / GBN, S_LEN / GBM);        // (4, 32) = 128 CTAs
    gemm_mma<float><<<ggrid, 256, GEMM_SMEM>>>(Xr, Wr + 0 * DM * DM, Qb);
    gemm_mma<float><<<ggrid, 256, GEMM_SMEM>>>(Xr, Wr + 1 * DM * DM, Kb);
    gemm_mma<__half><<<ggrid, 256, GEMM_SMEM>>>(Xr, Wr + 2 * DM * DM, Vh);

    int rope_threads = S_LEN * (DM / 2);
    rope_kernel<<<(rope_threads + 255) / 256, 256>>>(Qb, Kb, pos);

    flash_mma<<<(S_LEN / 64) * NHEADS, 128, FLASH_SMEM>>>(Qb, Kb, Vh, Ab);

    gemm_mma<float><<<ggrid, 256, GEMM_SMEM>>>(Ab, Wr + 3 * DM * DM, out);
}

// round 6
// speedup vs baseline: 8.7963x; 1.6286x over previous
#include <cuda_runtime.h>
#include <math.h>
#include <cstdint>
#include <cuda_fp16.h>

#define S_LEN    4096
#define DM       1024
#define NHEADS   16
#define HDIM     64

// Scratch (allocation-free rule: __device__ globals)
__device__ __half g_Xh[S_LEN * DM];
__device__ __half g_Wh[4 * DM * DM];
__device__ __half g_Qh[S_LEN * DM];
__device__ __half g_Kh[S_LEN * DM];
__device__ __half g_Vh[S_LEN * DM];
__device__ __half g_Ah[S_LEN * DM];
__device__ float  g_invfreq[HDIM / 2];

struct OutPtrs { void* p[3]; };

// ===========================================================================
// Helpers
// ===========================================================================
__device__ __forceinline__ uint32_t smem_u32(const void* p) {
    uint32_t a;
    asm("{ .reg .u64 t; cvta.to.shared.u64 t, %1; cvt.u32.u64 %0, t; }"
        : "=r"(a) : "l"(p));
    return a;
}
__device__ __forceinline__ void cp_async16(uint32_t s, const void* g) {
    asm volatile("cp.async.cg.shared.global [%0], [%1], 16;" :: "r"(s), "l"(g));
}
#define CP_ASYNC_COMMIT()  asm volatile("cp.async.commit_group;" ::: "memory")
#define CP_ASYNC_WAIT(n)   asm volatile("cp.async.wait_group %0;" :: "n"(n) : "memory")

__device__ __forceinline__ void mma_f16(float* c, uint32_t a0, uint32_t a1,
                                        uint32_t a2, uint32_t a3,
                                        uint32_t b0, uint32_t b1) {
    asm volatile(
        "mma.sync.aligned.m16n8k16.row.col.f32.f16.f16.f32 "
        "{%0,%1,%2,%3}, {%4,%5,%6,%7}, {%8,%9}, {%0,%1,%2,%3};"
        : "+f"(c[0]), "+f"(c[1]), "+f"(c[2]), "+f"(c[3])
        : "r"(a0), "r"(a1), "r"(a2), "r"(a3), "r"(b0), "r"(b1));
}
__device__ __forceinline__ void ldmatrix_x4(uint32_t& r0, uint32_t& r1,
                                            uint32_t& r2, uint32_t& r3, uint32_t addr) {
    asm volatile("ldmatrix.sync.aligned.m8n8.x4.shared.b16 {%0,%1,%2,%3}, [%4];"
                 : "=r"(r0), "=r"(r1), "=r"(r2), "=r"(r3) : "r"(addr));
}
__device__ __forceinline__ void ldmatrix_x2_trans(uint32_t& b0, uint32_t& b1, uint32_t addr) {
    asm volatile("ldmatrix.sync.aligned.m8n8.x2.trans.shared.b16 {%0,%1}, [%2];"
                 : "=r"(b0), "=r"(b1) : "r"(addr));
}
__device__ __forceinline__ uint32_t h2pack(float lo, float hi) {
    __half2 h = __floats2half2_rn(lo, hi);
    return *(uint32_t*)&h;
}

// ===========================================================================
// fp32 -> fp16 conversion
// ===========================================================================
__global__ __launch_bounds__(256) void cvt_half_kernel(
    __half2* __restrict__ dst, const float2* __restrict__ src, int n2)
{
    int i = blockIdx.x * blockDim.x + threadIdx.x;
    if (i < n2) {
        float2 v = src[i];
        dst[i] = __floats2half2_rn(v.x, v.y);
    }
}

// ---------------------------------------------------------------------------
// inv_freq in double precision
// ---------------------------------------------------------------------------
__global__ void freq_kernel() {
    int j = threadIdx.x;
    if (j < HDIM / 2) {
        double e = -(double)j / 32.0 * log(10000.0);
        g_invfreq[j] = (float)exp(e);
    }
}

// ---------------------------------------------------------------------------
// RoPE on fp16 Q/K (fp32 math). Q gets 1/8 prescale.
// ---------------------------------------------------------------------------
__global__ __launch_bounds__(256) void rope_h(
    __half2* __restrict__ Q2, __half2* __restrict__ K2, const int* __restrict__ pos)
{
    int idx = blockIdx.x * blockDim.x + threadIdx.x;
    if (idx >= S_LEN * (DM / 2)) return;
    int s = idx >> 9;
    int p = idx & 511;
    int h = p >> 5;
    int j = p & 31;
    float ang = (float)pos[s] * g_invfreq[j];
    float sn, cs;
    sincosf(ang, &sn, &cs);
    int base2 = (s << 9) + (h << 5) + j;   // half2 index of pair (2j, 2j+1)
    float2 q = __half22float2(Q2[base2]);
    float2 k = __half22float2(K2[base2]);
    Q2[base2] = __floats2half2_rn(0.125f * (q.x * cs - q.y * sn),
                                  0.125f * (q.x * sn + q.y * cs));
    K2[base2] = __floats2half2_rn(k.x * cs - k.y * sn,
                                  k.x * sn + k.y * cs);
}

// ===========================================================================
// fp16 mma.sync GEMM (NT): C[M, n] = A[M,K] * B[n,K]^T  (fp32 accumulate).
// 128x128x32h tile, 256 threads (8 warps 4x2), warp tile 32x64.
// ldmatrix.x4 fragment loads, single-sync cp.async double buffer.
// Supports merged multi-matrix B (QKV): out ptr = outs.p[col0 >> 10].
// ===========================================================================
#define HBM 128
#define HBN 128
#define HBK 32                       // halves
#define HKT (DM / HBK)               // 32
#define HSTR 40                      // smem row stride (halves)

template <typename OutT>
__global__ __launch_bounds__(256) void hgemm(
    const __half* __restrict__ A, const __half* __restrict__ B, OutPtrs outs)
{
    __shared__ __align__(16) __half Ah[2][HBM][HSTR];
    __shared__ __align__(16) __half Bh[2][HBN][HSTR];
    const uint32_t ah_u = smem_u32(Ah);
    const uint32_t bh_u = smem_u32(Bh);

    const int tid  = threadIdx.x;
    const int wid  = tid >> 5;
    const int lane = tid & 31;
    const int wm   = wid >> 1;        // 0..3
    const int wn   = wid & 1;         // 0..1
    const int r    = lane >> 2;
    const int c4   = lane & 3;
    const int row0  = blockIdx.y * HBM;
    const int col0g = blockIdx.x * HBN;

    OutT* C = (OutT*)outs.p[col0g >> 10];
    const int colW = col0g & (DM - 1);

    // per-lane ldmatrix address components
    const int lrow = ((lane >> 3) & 1) * 8 + (lane & 7);
    const int lcol = ((lane >> 4) & 1) * 8;

    float acc[2][8][4];
#pragma unroll
    for (int mt = 0; mt < 2; mt++)
#pragma unroll
        for (int nt = 0; nt < 8; nt++)
#pragma unroll
            for (int i = 0; i < 4; i++) acc[mt][nt][i] = 0.f;

    auto load_tile = [&](int kt, int buf) {
        const int k0 = kt * HBK;
#pragma unroll
        for (int i = 0; i < 2; i++) {                 // A: 512 x 16B chunks
            int chunk = tid + i * 256;
            int m = chunk >> 2, c8 = (chunk & 3) * 8;
            cp_async16(ah_u + (uint32_t)((((buf * HBM) + m) * HSTR + c8) * 2),
                       A + (size_t)(row0 + m) * DM + k0 + c8);
        }
#pragma unroll
        for (int i = 0; i < 2; i++) {                 // B: 512 x 16B chunks
            int chunk = tid + i * 256;
            int m = chunk >> 2, c8 = (chunk & 3) * 8;
            cp_async16(bh_u + (uint32_t)((((buf * HBN) + m) * HSTR + c8) * 2),
                       B + (size_t)(col0g + m) * DM + k0 + c8);
        }
        CP_ASYNC_COMMIT();
    };

    load_tile(0, 0);

    for (int kt = 0; kt < HKT; kt++) {
        const int buf = kt & 1;
        CP_ASYNC_WAIT(0);
        __syncthreads();
        if (kt + 1 < HKT) load_tile(kt + 1, buf ^ 1);

#pragma unroll
        for (int s = 0; s < 2; s++) {                 // two k16 steps
            const int k0 = s * 16;
            uint32_t au[2][4], bu[8][2];
#pragma unroll
            for (int mt = 0; mt < 2; mt++) {
                int row = wm * 32 + mt * 16 + lrow;
                uint32_t addr = ah_u +
                    (uint32_t)(((buf * HBM + row) * HSTR + k0 + lcol) * 2);
                ldmatrix_x4(au[mt][0], au[mt][1], au[mt][2], au[mt][3], addr);
            }
#pragma unroll
            for (int ntp = 0; ntp < 4; ntp++) {
                int row = wn * 64 + ntp * 16 + lrow;
                uint32_t addr = bh_u +
                    (uint32_t)(((buf * HBN + row) * HSTR + k0 + lcol) * 2);
                uint32_t t0, t1, t2, t3;
                ldmatrix_x4(t0, t1, t2, t3, addr);
                bu[2 * ntp][0] = t0;     bu[2 * ntp][1] = t2;
                bu[2 * ntp + 1][0] = t1; bu[2 * ntp + 1][1] = t3;
            }
#pragma unroll
            for (int mt = 0; mt < 2; mt++)
#pragma unroll
                for (int nt = 0; nt < 8; nt++)
                    mma_f16(acc[mt][nt], au[mt][0], au[mt][1], au[mt][2], au[mt][3],
                            bu[nt][0], bu[nt][1]);
        }
    }

#pragma unroll
    for (int mt = 0; mt < 2; mt++) {
#pragma unroll
        for (int nt = 0; nt < 8; nt++) {
            int row = row0 + wm * 32 + mt * 16 + r;
            int col = colW + wn * 64 + nt * 8 + c4 * 2;
            if (sizeof(OutT) == 4) {
                *(float2*)((float*)C + (size_t)row * DM + col) =
                    make_float2(acc[mt][nt][0], acc[mt][nt][1]);
                *(float2*)((float*)C + (size_t)(row + 8) * DM + col) =
                    make_float2(acc[mt][nt][2], acc[mt][nt][3]);
            } else {
                *(__half2*)((__half*)C + (size_t)row * DM + col) =
                    __floats2half2_rn(acc[mt][nt][0], acc[mt][nt][1]);
                *(__half2*)((__half*)C + (size_t)(row + 8) * DM + col) =
                    __floats2half2_rn(acc[mt][nt][2], acc[mt][nt][3]);
            }
        }
    }
}

// ===========================================================================
// fp16 tensor-core causal flash attention, double-buffered cp.async K/V.
// S = QK^T via m16n8k16.f16 (ldmatrix frags); softmax fp32 in C-frags;
// O += P.V via m16n8k16.f16 with P register-packed, V via ldmatrix.trans.
// ===========================================================================
#define FSTR 72                      // smem row stride (halves)

__global__ __launch_bounds__(128) void flash_h(
    const __half* __restrict__ Q, const __half* __restrict__ K,
    const __half* __restrict__ V, __half* __restrict__ O)
{
    __shared__ __align__(16) __half Ks[2][64][FSTR];
    __shared__ __align__(16) __half Vs[2][64][FSTR];
    const uint32_t ks_u = smem_u32(Ks);
    const uint32_t vs_u = smem_u32(Vs);

    const int tid  = threadIdx.x;
    const int warp = tid >> 5;
    const int lane = tid & 31;
    const int r    = lane >> 2;
    const int c    = lane & 3;
    const int qblk = (gridDim.x >> 4) - 1 - (int)(blockIdx.x >> 4);  // heavy first
    const int h    = blockIdx.x & 15;
    const int qbase = qblk * 64;
    const int w16   = warp * 16;
    const int lrow  = ((lane >> 3) & 1) * 8 + (lane & 7);
    const int lcol  = ((lane >> 4) & 1) * 8;

    // ---- stage Q (fp16, pre-scaled) into Ks[0], extract A-frags -----------
    for (int i = 0; i < 4; i++) {
        int chunk = tid + i * 128;
        int row = chunk >> 3, c8 = (chunk & 7) * 8;
        *(float4*)&Ks[0][row][c8] =
            *(const float4*)(Q + (size_t)(qbase + row) * DM + h * HDIM + c8);
    }
    __syncthreads();

    uint32_t qa[4][4];
#pragma unroll
    for (int g = 0; g < 4; g++) {
        uint32_t addr = ks_u + (uint32_t)(((w16 + lrow) * FSTR + g * 16 + lcol) * 2);
        ldmatrix_x4(qa[g][0], qa[g][1], qa[g][2], qa[g][3], addr);
    }
    __syncthreads();

    auto load_tile = [&](int buf, int kt) {
#pragma unroll
        for (int i = 0; i < 4; i++) {                 // K: 512 chunks
            int chunk = tid + i * 128;
            int row = chunk >> 3, c8 = (chunk & 7) * 8;
            cp_async16(ks_u + (uint32_t)(((buf * 64 + row) * FSTR + c8) * 2),
                       K + (size_t)(kt + row) * DM + h * HDIM + c8);
        }
#pragma unroll
        for (int i = 0; i < 4; i++) {                 // V: 512 chunks
            int chunk = tid + i * 128;
            int row = chunk >> 3, c8 = (chunk & 7) * 8;
            cp_async16(vs_u + (uint32_t)(((buf * 64 + row) * FSTR + c8) * 2),
                       V + (size_t)(kt + row) * DM + h * HDIM + c8);
        }
        CP_ASYNC_COMMIT();
    };

    float acc[8][4];
#pragma unroll
    for (int nt = 0; nt < 8; nt++)
#pragma unroll
        for (int i = 0; i < 4; i++) acc[nt][i] = 0.f;
    float m0 = -1e30f, m1 = -1e30f, l0 = 0.f, l1 = 0.f;

    load_tile(0, 0);

    for (int kt = 0; kt <= qbase; kt += 64) {
        const int buf = (kt >> 6) & 1;
        CP_ASYNC_WAIT(0);
        __syncthreads();
        if (kt + 64 <= qbase) load_tile(buf ^ 1, kt + 64);

        const uint32_t kb_u = ks_u + (uint32_t)(buf * 64 * FSTR * 2);
        const uint32_t vb_u = vs_u + (uint32_t)(buf * 64 * FSTR * 2);

        // ---- S = Q K^T ----------------------------------------------------
        float sc[8][4];
#pragma unroll
        for (int nt = 0; nt < 8; nt++)
            sc[nt][0] = sc[nt][1] = sc[nt][2] = sc[nt][3] = 0.f;
#pragma unroll
        for (int g = 0; g < 4; g++) {
#pragma unroll
            for (int ntp = 0; ntp < 4; ntp++) {
                uint32_t addr = kb_u +
                    (uint32_t)(((ntp * 16 + lrow) * FSTR + g * 16 + lcol) * 2);
                uint32_t t0, t1, t2, t3;
                ldmatrix_x4(t0, t1, t2, t3, addr);
                mma_f16(sc[2 * ntp],     qa[g][0], qa[g][1], qa[g][2], qa[g][3], t0, t2);
                mma_f16(sc[2 * ntp + 1], qa[g][0], qa[g][1], qa[g][2], qa[g][3], t1, t3);
            }
        }

        // ---- causal mask on the diagonal tile ------------------------------
        if (kt == qbase) {
            const int qr0 = w16 + r, qr1 = qr0 + 8;
#pragma unroll
            for (int nt = 0; nt < 8; nt++) {
                int cb = nt * 8 + 2 * c;
                if (cb     > qr0) sc[nt][0] = -1e30f;
                if (cb + 1 > qr0) sc[nt][1] = -1e30f;
                if (cb     > qr1) sc[nt][2] = -1e30f;
                if (cb + 1 > qr1) sc[nt][3] = -1e30f;
            }
        }

        // ---- online softmax ------------------------------------------------
        float mx0 = -1e30f, mx1 = -1e30f;
#pragma unroll
        for (int nt = 0; nt < 8; nt++) {
            mx0 = fmaxf(mx0, fmaxf(sc[nt][0], sc[nt][1]));
            mx1 = fmaxf(mx1, fmaxf(sc[nt][2], sc[nt][3]));
        }
        mx0 = fmaxf(mx0, __shfl_xor_sync(0xffffffffu, mx0, 1));
        mx0 = fmaxf(mx0, __shfl_xor_sync(0xffffffffu, mx0, 2));
        mx1 = fmaxf(mx1, __shfl_xor_sync(0xffffffffu, mx1, 1));
        mx1 = fmaxf(mx1, __shfl_xor_sync(0xffffffffu, mx1, 2));

        float nm0 = fmaxf(m0, mx0), nm1 = fmaxf(m1, mx1);
        float s0 = __expf(m0 - nm0), s1 = __expf(m1 - nm1);
        m0 = nm0; m1 = nm1;

        float rs0 = 0.f, rs1 = 0.f;
#pragma unroll
        for (int nt = 0; nt < 8; nt++) {
            sc[nt][0] = __expf(sc[nt][0] - nm0);
            sc[nt][1] = __expf(sc[nt][1] - nm0);
            sc[nt][2] = __expf(sc[nt][2] - nm1);
            sc[nt][3] = __expf(sc[nt][3] - nm1);
            rs0 += sc[nt][0] + sc[nt][1];
            rs1 += sc[nt][2] + sc[nt][3];
        }
        rs0 += __shfl_xor_sync(0xffffffffu, rs0, 1);
        rs0 += __shfl_xor_sync(0xffffffffu, rs0, 2);
        rs1 += __shfl_xor_sync(0xffffffffu, rs1, 1);
        rs1 += __shfl_xor_sync(0xffffffffu, rs1, 2);
        l0 = l0 * s0 + rs0;
        l1 = l1 * s1 + rs1;

#pragma unroll
        for (int nt = 0; nt < 8; nt++) {
            acc[nt][0] *= s0; acc[nt][1] *= s0;
            acc[nt][2] *= s1; acc[nt][3] *= s1;
        }

        // ---- O += P.V ------------------------------------------------------
#pragma unroll
        for (int kk = 0; kk < 4; kk++) {
            uint32_t a0 = h2pack(sc[2 * kk][0],     sc[2 * kk][1]);
            uint32_t a1 = h2pack(sc[2 * kk][2],     sc[2 * kk][3]);
            uint32_t a2 = h2pack(sc[2 * kk + 1][0], sc[2 * kk + 1][1]);
            uint32_t a3 = h2pack(sc[2 * kk + 1][2], sc[2 * kk + 1][3]);
            const int vrow = kk * 16 + (lane & 15);
#pragma unroll
            for (int nd = 0; nd < 8; nd++) {
                uint32_t baddr = vb_u + (uint32_t)((vrow * FSTR + nd * 8) * 2);
                uint32_t b0, b1;
                ldmatrix_x2_trans(b0, b1, baddr);
                mma_f16(acc[nd], a0, a1, a2, a3, b0, b1);
            }
        }
    }

    // ---- epilogue: fp16 attn for the out-projection -----------------------
    float i0 = 1.f / l0, i1 = 1.f / l1;
    const int row0 = qbase + w16 + r;
#pragma unroll
    for (int nt = 0; nt < 8; nt++) {
        int col = h * HDIM + nt * 8 + 2 * c;
        *(__half2*)&O[(size_t)row0 * DM + col] =
            __floats2half2_rn(acc[nt][0] * i0, acc[nt][1] * i0);
        *(__half2*)&O[(size_t)(row0 + 8) * DM + col] =
            __floats2half2_rn(acc[nt][2] * i1, acc[nt][3] * i1);
    }
}

// ---------------------------------------------------------------------------
// Launcher
// ---------------------------------------------------------------------------
extern "C" void kernel_launch(void* const* d_in, const int* in_sizes, int n_in,
                              void* d_out, int out_size)
{
    const float* x  = (const float*)d_in[0];
    const float* Wq = (const float*)d_in[1];
    const float* Wk = (const float*)d_in[2];
    const float* Wv = (const float*)d_in[3];
    const float* Wo = (const float*)d_in[4];
    const int*  pos = (const int*)  d_in[5];
    float* out = (float*)d_out;

    __half *Xh, *Wh, *Qh, *Kh, *Vh, *Ah;
    cudaGetSymbolAddress((void**)&Xh, g_Xh);
    cudaGetSymbolAddress((void**)&Wh, g_Wh);
    cudaGetSymbolAddress((void**)&Qh, g_Qh);
    cudaGetSymbolAddress((void**)&Kh, g_Kh);
    cudaGetSymbolAddress((void**)&Vh, g_Vh);
    cudaGetSymbolAddress((void**)&Ah, g_Ah);

    const int nx2 = S_LEN * DM / 2;       // 2M half2
    const int nw2 = DM * DM / 2;          // 512K half2
    cvt_half_kernel<<<(nx2 + 255) / 256, 256>>>((__half2*)Xh, (const float2*)x, nx2);
    cvt_half_kernel<<<(nw2 + 255) / 256, 256>>>((__half2*)(Wh + 0 * DM * DM), (const float2*)Wq, nw2);
    cvt_half_kernel<<<(nw2 + 255) / 256, 256>>>((__half2*)(Wh + 1 * DM * DM), (const float2*)Wk, nw2);
    cvt_half_kernel<<<(nw2 + 255) / 256, 256>>>((__half2*)(Wh + 2 * DM * DM), (const float2*)Wv, nw2);
    cvt_half_kernel<<<(nw2 + 255) / 256, 256>>>((__half2*)(Wh + 3 * DM * DM), (const float2*)Wo, nw2);
    freq_kernel<<<1, 32>>>();

    // merged QKV GEMM: B = [Wq; Wk; Wv], N = 3072
    OutPtrs qkv; qkv.p[0] = Qh; qkv.p[1] = Kh; qkv.p[2] = Vh;
    dim3 qkv_grid(3 * DM / HBN, S_LEN / HBM);     // (24, 32)
    hgemm<__half><<<qkv_grid, 256>>>(Xh, Wh, qkv);

    int rope_threads = S_LEN * (DM / 2);
    rope_h<<<(rope_threads + 255) / 256, 256>>>((__half2*)Qh, (__half2*)Kh, pos);

    flash_h<<<(S_LEN / 64) * NHEADS, 128>>>(Qh, Kh, Vh, Ah);

    OutPtrs op; op.p[0] = out; op.p[1] = out; op.p[2] = out;
    dim3 out_grid(DM / HBN, S_LEN / HBM);         // (8, 32)
    hgemm<float><<<out_grid, 256>>>(Ah, Wh + 3 * DM * DM, op);
}

// round 7
// speedup vs baseline: 8.8446x; 1.0055x over previous
#include <cuda_runtime.h>
#include <math.h>
#include <cstdint>
#include <cuda_fp16.h>

#define S_LEN    4096
#define DM       1024
#define NHEADS   16
#define HDIM     64

// Scratch (allocation-free rule: __device__ globals)
__device__ __half g_Xh[S_LEN * DM];
__device__ __half g_Wh[4 * DM * DM];
__device__ __half g_Qh[S_LEN * DM];
__device__ __half g_Kh[S_LEN * DM];
__device__ __half g_Vh[S_LEN * DM];
__device__ __half g_Ah[S_LEN * DM];
__device__ float2 g_cs[S_LEN * 32];        // (cos, sin) per (pos, j)

struct OutPtrs { void* p[3]; };
struct SrcPtrs { const float2* p[5]; };

// ===========================================================================
// Helpers
// ===========================================================================
__device__ __forceinline__ uint32_t smem_u32(const void* p) {
    uint32_t a;
    asm("{ .reg .u64 t; cvta.to.shared.u64 t, %1; cvt.u32.u64 %0, t; }"
        : "=r"(a) : "l"(p));
    return a;
}
__device__ __forceinline__ void cp_async16(uint32_t s, const void* g) {
    asm volatile("cp.async.cg.shared.global [%0], [%1], 16;" :: "r"(s), "l"(g));
}
#define CP_ASYNC_COMMIT()  asm volatile("cp.async.commit_group;" ::: "memory")
#define CP_ASYNC_WAIT(n)   asm volatile("cp.async.wait_group %0;" :: "n"(n) : "memory")

__device__ __forceinline__ void mma_f16(float* c, uint32_t a0, uint32_t a1,
                                        uint32_t a2, uint32_t a3,
                                        uint32_t b0, uint32_t b1) {
    asm volatile(
        "mma.sync.aligned.m16n8k16.row.col.f32.f16.f16.f32 "
        "{%0,%1,%2,%3}, {%4,%5,%6,%7}, {%8,%9}, {%0,%1,%2,%3};"
        : "+f"(c[0]), "+f"(c[1]), "+f"(c[2]), "+f"(c[3])
        : "r"(a0), "r"(a1), "r"(a2), "r"(a3), "r"(b0), "r"(b1));
}
__device__ __forceinline__ void ldmatrix_x4(uint32_t& r0, uint32_t& r1,
                                            uint32_t& r2, uint32_t& r3, uint32_t addr) {
    asm volatile("ldmatrix.sync.aligned.m8n8.x4.shared.b16 {%0,%1,%2,%3}, [%4];"
                 : "=r"(r0), "=r"(r1), "=r"(r2), "=r"(r3) : "r"(addr));
}
__device__ __forceinline__ void ldmatrix_x2_trans(uint32_t& b0, uint32_t& b1, uint32_t addr) {
    asm volatile("ldmatrix.sync.aligned.m8n8.x2.trans.shared.b16 {%0,%1}, [%2];"
                 : "=r"(b0), "=r"(b1) : "r"(addr));
}
__device__ __forceinline__ uint32_t h2pack(float lo, float hi) {
    __half2 h = __floats2half2_rn(lo, hi);
    return *(uint32_t*)&h;
}

// ===========================================================================
// One-shot conversion of x + 4 weights to fp16 (single launch)
// ===========================================================================
#define NX2 (S_LEN * DM / 2)          // 2097152 float2 in x
#define NW2 (DM * DM / 2)             // 524288 float2 per weight
#define NALL2 (NX2 + 4 * NW2)

__global__ __launch_bounds__(256) void cvt_all_kernel(SrcPtrs srcs)
{
    int i = blockIdx.x * blockDim.x + threadIdx.x;
    if (i >= NALL2) return;
    float2 v;
    __half2* dst;
    if (i < NX2) {
        v = srcs.p[0][i];
        dst = (__half2*)g_Xh + i;
    } else {
        int rel = i - NX2;
        int w = rel / NW2;
        int off = rel - w * NW2;
        v = srcs.p[1 + w][off];
        dst = (__half2*)g_Wh + w * NW2 + off;
    }
    *dst = __floats2half2_rn(v.x, v.y);
}

// ---------------------------------------------------------------------------
// cos/sin table: g_cs[s*32 + j] = (cos, sin)(pos[s] * theta^{-j/32})
// ---------------------------------------------------------------------------
__global__ __launch_bounds__(256) void cs_kernel(const int* __restrict__ pos)
{
    int idx = blockIdx.x * blockDim.x + threadIdx.x;
    if (idx >= S_LEN * 32) return;
    int s = idx >> 5;
    int j = idx & 31;
    double invf = exp(-(double)j / 32.0 * log(10000.0));
    float ang = (float)pos[s] * (float)invf;
    float sn, cs;
    sincosf(ang, &sn, &cs);
    g_cs[idx] = make_float2(cs, sn);
}

// ===========================================================================
// fp16 mma.sync GEMM (NT), fp32 accumulate, 128x128x32h tile, 256 threads.
// ROPE=true fuses the RoPE rotation (+1/8 Q prescale) into the epilogue
// for the Q (mat 0) and K (mat 1) column blocks of the merged QKV GEMM.
// ===========================================================================
#define HBM 128
#define HBN 128
#define HBK 32
#define HKT (DM / HBK)               // 32
#define HSTR 40

template <typename OutT, bool ROPE>
__global__ __launch_bounds__(256) void hgemm(
    const __half* __restrict__ A, const __half* __restrict__ B, OutPtrs outs)
{
    __shared__ __align__(16) __half Ah[2][HBM][HSTR];
    __shared__ __align__(16) __half Bh[2][HBN][HSTR];
    const uint32_t ah_u = smem_u32(Ah);
    const uint32_t bh_u = smem_u32(Bh);

    const int tid  = threadIdx.x;
    const int wid  = tid >> 5;
    const int lane = tid & 31;
    const int wm   = wid >> 1;
    const int wn   = wid & 1;
    const int r    = lane >> 2;
    const int c4   = lane & 3;
    const int row0  = blockIdx.y * HBM;
    const int col0g = blockIdx.x * HBN;

    const int mat = col0g >> 10;
    OutT* C = (OutT*)outs.p[mat];
    const int colW = col0g & (DM - 1);

    const int lrow = ((lane >> 3) & 1) * 8 + (lane & 7);
    const int lcol = ((lane >> 4) & 1) * 8;

    float acc[2][8][4];
#pragma unroll
    for (int mt = 0; mt < 2; mt++)
#pragma unroll
        for (int nt = 0; nt < 8; nt++)
#pragma unroll
            for (int i = 0; i < 4; i++) acc[mt][nt][i] = 0.f;

    auto load_tile = [&](int kt, int buf) {
        const int k0 = kt * HBK;
#pragma unroll
        for (int i = 0; i < 2; i++) {
            int chunk = tid + i * 256;
            int m = chunk >> 2, c8 = (chunk & 3) * 8;
            cp_async16(ah_u + (uint32_t)((((buf * HBM) + m) * HSTR + c8) * 2),
                       A + (size_t)(row0 + m) * DM + k0 + c8);
        }
#pragma unroll
        for (int i = 0; i < 2; i++) {
            int chunk = tid + i * 256;
            int m = chunk >> 2, c8 = (chunk & 3) * 8;
            cp_async16(bh_u + (uint32_t)((((buf * HBN) + m) * HSTR + c8) * 2),
                       B + (size_t)(col0g + m) * DM + k0 + c8);
        }
        CP_ASYNC_COMMIT();
    };

    load_tile(0, 0);

    for (int kt = 0; kt < HKT; kt++) {
        const int buf = kt & 1;
        CP_ASYNC_WAIT(0);
        __syncthreads();
        if (kt + 1 < HKT) load_tile(kt + 1, buf ^ 1);

#pragma unroll
        for (int s = 0; s < 2; s++) {
            const int k0 = s * 16;
            uint32_t au[2][4], bu[8][2];
#pragma unroll
            for (int mt = 0; mt < 2; mt++) {
                int row = wm * 32 + mt * 16 + lrow;
                uint32_t addr = ah_u +
                    (uint32_t)(((buf * HBM + row) * HSTR + k0 + lcol) * 2);
                ldmatrix_x4(au[mt][0], au[mt][1], au[mt][2], au[mt][3], addr);
            }
#pragma unroll
            for (int ntp = 0; ntp < 4; ntp++) {
                int row = wn * 64 + ntp * 16 + lrow;
                uint32_t addr = bh_u +
                    (uint32_t)(((buf * HBN + row) * HSTR + k0 + lcol) * 2);
                uint32_t t0, t1, t2, t3;
                ldmatrix_x4(t0, t1, t2, t3, addr);
                bu[2 * ntp][0] = t0;     bu[2 * ntp][1] = t2;
                bu[2 * ntp + 1][0] = t1; bu[2 * ntp + 1][1] = t3;
            }
#pragma unroll
            for (int mt = 0; mt < 2; mt++)
#pragma unroll
                for (int nt = 0; nt < 8; nt++)
                    mma_f16(acc[mt][nt], au[mt][0], au[mt][1], au[mt][2], au[mt][3],
                            bu[nt][0], bu[nt][1]);
        }
    }

    const bool do_rope = ROPE && (mat < 2);
    const float qs = (mat == 0) ? 0.125f : 1.0f;

#pragma unroll
    for (int mt = 0; mt < 2; mt++) {
#pragma unroll
        for (int nt = 0; nt < 8; nt++) {
            int row = row0 + wm * 32 + mt * 16 + r;
            int col = colW + wn * 64 + nt * 8 + c4 * 2;
            float v0 = acc[mt][nt][0], v1 = acc[mt][nt][1];
            float v2 = acc[mt][nt][2], v3 = acc[mt][nt][3];
            if (do_rope) {
                int j = nt * 4 + c4;                 // head pair index
                float2 csA = g_cs[row * 32 + j];
                float2 csB = g_cs[(row + 8) * 32 + j];
                float t0 = v0 * csA.x - v1 * csA.y;
                float t1 = v0 * csA.y + v1 * csA.x;
                float t2 = v2 * csB.x - v3 * csB.y;
                float t3 = v2 * csB.y + v3 * csB.x;
                v0 = t0 * qs; v1 = t1 * qs; v2 = t2 * qs; v3 = t3 * qs;
            }
            if (sizeof(OutT) == 4) {
                *(float2*)((float*)C + (size_t)row * DM + col) = make_float2(v0, v1);
                *(float2*)((float*)C + (size_t)(row + 8) * DM + col) = make_float2(v2, v3);
            } else {
                *(__half2*)((__half*)C + (size_t)row * DM + col) =
                    __floats2half2_rn(v0, v1);
                *(__half2*)((__half*)C + (size_t)(row + 8) * DM + col) =
                    __floats2half2_rn(v2, v3);
            }
        }
    }
}

// ===========================================================================
// fp16 tensor-core causal flash attention (Q pre-scaled by 1/8 in QKV gemm).
// exp2-based softmax: scores scaled by log2(e) once per tile.
// ===========================================================================
#define FSTR 72

__global__ __launch_bounds__(128) void flash_h(
    const __half* __restrict__ Q, const __half* __restrict__ K,
    const __half* __restrict__ V, __half* __restrict__ O)
{
    __shared__ __align__(16) __half Ks[2][64][FSTR];
    __shared__ __align__(16) __half Vs[2][64][FSTR];
    const uint32_t ks_u = smem_u32(Ks);
    const uint32_t vs_u = smem_u32(Vs);

    const int tid  = threadIdx.x;
    const int warp = tid >> 5;
    const int lane = tid & 31;
    const int r    = lane >> 2;
    const int c    = lane & 3;
    const int qblk = (gridDim.x >> 4) - 1 - (int)(blockIdx.x >> 4);  // heavy first
    const int h    = blockIdx.x & 15;
    const int qbase = qblk * 64;
    const int w16   = warp * 16;
    const int lrow  = ((lane >> 3) & 1) * 8 + (lane & 7);
    const int lcol  = ((lane >> 4) & 1) * 8;
    const float L2E = 1.4426950408889634f;

    // ---- stage Q into Ks[0], extract A-frags ------------------------------
    for (int i = 0; i < 4; i++) {
        int chunk = tid + i * 128;
        int row = chunk >> 3, c8 = (chunk & 7) * 8;
        *(float4*)&Ks[0][row][c8] =
            *(const float4*)(Q + (size_t)(qbase + row) * DM + h * HDIM + c8);
    }
    __syncthreads();

    uint32_t qa[4][4];
#pragma unroll
    for (int g = 0; g < 4; g++) {
        uint32_t addr = ks_u + (uint32_t)(((w16 + lrow) * FSTR + g * 16 + lcol) * 2);
        ldmatrix_x4(qa[g][0], qa[g][1], qa[g][2], qa[g][3], addr);
    }
    __syncthreads();

    auto load_tile = [&](int buf, int kt) {
#pragma unroll
        for (int i = 0; i < 4; i++) {
            int chunk = tid + i * 128;
            int row = chunk >> 3, c8 = (chunk & 7) * 8;
            cp_async16(ks_u + (uint32_t)(((buf * 64 + row) * FSTR + c8) * 2),
                       K + (size_t)(kt + row) * DM + h * HDIM + c8);
        }
#pragma unroll
        for (int i = 0; i < 4; i++) {
            int chunk = tid + i * 128;
            int row = chunk >> 3, c8 = (chunk & 7) * 8;
            cp_async16(vs_u + (uint32_t)(((buf * 64 + row) * FSTR + c8) * 2),
                       V + (size_t)(kt + row) * DM + h * HDIM + c8);
        }
        CP_ASYNC_COMMIT();
    };

    float acc[8][4];
#pragma unroll
    for (int nt = 0; nt < 8; nt++)
#pragma unroll
        for (int i = 0; i < 4; i++) acc[nt][i] = 0.f;
    float m0 = -1e30f, m1 = -1e30f, l0 = 0.f, l1 = 0.f;

    load_tile(0, 0);

    for (int kt = 0; kt <= qbase; kt += 64) {
        const int buf = (kt >> 6) & 1;
        CP_ASYNC_WAIT(0);
        __syncthreads();
        if (kt + 64 <= qbase) load_tile(buf ^ 1, kt + 64);

        const uint32_t kb_u = ks_u + (uint32_t)(buf * 64 * FSTR * 2);
        const uint32_t vb_u = vs_u + (uint32_t)(buf * 64 * FSTR * 2);

        // ---- S = Q K^T (in log2 domain after x L2E) ------------------------
        float sc[8][4];
#pragma unroll
        for (int nt = 0; nt < 8; nt++)
            sc[nt][0] = sc[nt][1] = sc[nt][2] = sc[nt][3] = 0.f;
#pragma unroll
        for (int g = 0; g < 4; g++) {
#pragma unroll
            for (int ntp = 0; ntp < 4; ntp++) {
                uint32_t addr = kb_u +
                    (uint32_t)(((ntp * 16 + lrow) * FSTR + g * 16 + lcol) * 2);
                uint32_t t0, t1, t2, t3;
                ldmatrix_x4(t0, t1, t2, t3, addr);
                mma_f16(sc[2 * ntp],     qa[g][0], qa[g][1], qa[g][2], qa[g][3], t0, t2);
                mma_f16(sc[2 * ntp + 1], qa[g][0], qa[g][1], qa[g][2], qa[g][3], t1, t3);
            }
        }
#pragma unroll
        for (int nt = 0; nt < 8; nt++) {
            sc[nt][0] *= L2E; sc[nt][1] *= L2E;
            sc[nt][2] *= L2E; sc[nt][3] *= L2E;
        }

        // ---- causal mask on the diagonal tile ------------------------------
        if (kt == qbase) {
            const int qr0 = w16 + r, qr1 = qr0 + 8;
#pragma unroll
            for (int nt = 0; nt < 8; nt++) {
                int cb = nt * 8 + 2 * c;
                if (cb     > qr0) sc[nt][0] = -1e30f;
                if (cb + 1 > qr0) sc[nt][1] = -1e30f;
                if (cb     > qr1) sc[nt][2] = -1e30f;
                if (cb + 1 > qr1) sc[nt][3] = -1e30f;
            }
        }

        // ---- online softmax (base-2) --------------------------------------
        float mx0 = -1e30f, mx1 = -1e30f;
#pragma unroll
        for (int nt = 0; nt < 8; nt++) {
            mx0 = fmaxf(mx0, fmaxf(sc[nt][0], sc[nt][1]));
            mx1 = fmaxf(mx1, fmaxf(sc[nt][2], sc[nt][3]));
        }
        mx0 = fmaxf(mx0, __shfl_xor_sync(0xffffffffu, mx0, 1));
        mx0 = fmaxf(mx0, __shfl_xor_sync(0xffffffffu, mx0, 2));
        mx1 = fmaxf(mx1, __shfl_xor_sync(0xffffffffu, mx1, 1));
        mx1 = fmaxf(mx1, __shfl_xor_sync(0xffffffffu, mx1, 2));

        float nm0 = fmaxf(m0, mx0), nm1 = fmaxf(m1, mx1);
        float s0 = exp2f(m0 - nm0), s1 = exp2f(m1 - nm1);
        m0 = nm0; m1 = nm1;

        float rs0 = 0.f, rs1 = 0.f;
#pragma unroll
        for (int nt = 0; nt < 8; nt++) {
            sc[nt][0] = exp2f(sc[nt][0] - nm0);
            sc[nt][1] = exp2f(sc[nt][1] - nm0);
            sc[nt][2] = exp2f(sc[nt][2] - nm1);
            sc[nt][3] = exp2f(sc[nt][3] - nm1);
            rs0 += sc[nt][0] + sc[nt][1];
            rs1 += sc[nt][2] + sc[nt][3];
        }
        rs0 += __shfl_xor_sync(0xffffffffu, rs0, 1);
        rs0 += __shfl_xor_sync(0xffffffffu, rs0, 2);
        rs1 += __shfl_xor_sync(0xffffffffu, rs1, 1);
        rs1 += __shfl_xor_sync(0xffffffffu, rs1, 2);
        l0 = l0 * s0 + rs0;
        l1 = l1 * s1 + rs1;

#pragma unroll
        for (int nt = 0; nt < 8; nt++) {
            acc[nt][0] *= s0; acc[nt][1] *= s0;
            acc[nt][2] *= s1; acc[nt][3] *= s1;
        }

        // ---- O += P.V ------------------------------------------------------
#pragma unroll
        for (int kk = 0; kk < 4; kk++) {
            uint32_t a0 = h2pack(sc[2 * kk][0],     sc[2 * kk][1]);
            uint32_t a1 = h2pack(sc[2 * kk][2],     sc[2 * kk][3]);
            uint32_t a2 = h2pack(sc[2 * kk + 1][0], sc[2 * kk + 1][1]);
            uint32_t a3 = h2pack(sc[2 * kk + 1][2], sc[2 * kk + 1][3]);
            const int vrow = kk * 16 + (lane & 15);
#pragma unroll
            for (int nd = 0; nd < 8; nd++) {
                uint32_t baddr = vb_u + (uint32_t)((vrow * FSTR + nd * 8) * 2);
                uint32_t b0, b1;
                ldmatrix_x2_trans(b0, b1, baddr);
                mma_f16(acc[nd], a0, a1, a2, a3, b0, b1);
            }
        }
    }

    // ---- epilogue ---------------------------------------------------------
    float i0 = 1.f / l0, i1 = 1.f / l1;
    const int row0 = qbase + w16 + r;
#pragma unroll
    for (int nt = 0; nt < 8; nt++) {
        int col = h * HDIM + nt * 8 + 2 * c;
        *(__half2*)&O[(size_t)row0 * DM + col] =
            __floats2half2_rn(acc[nt][0] * i0, acc[nt][1] * i0);
        *(__half2*)&O[(size_t)(row0 + 8) * DM + col] =
            __floats2half2_rn(acc[nt][2] * i1, acc[nt][3] * i1);
    }
}

// ---------------------------------------------------------------------------
// Launcher
// ---------------------------------------------------------------------------
extern "C" void kernel_launch(void* const* d_in, const int* in_sizes, int n_in,
                              void* d_out, int out_size)
{
    const float* x  = (const float*)d_in[0];
    const int*  pos = (const int*)  d_in[5];
    float* out = (float*)d_out;

    __half *Xh, *Wh, *Qh, *Kh, *Vh, *Ah;
    cudaGetSymbolAddress((void**)&Xh, g_Xh);
    cudaGetSymbolAddress((void**)&Wh, g_Wh);
    cudaGetSymbolAddress((void**)&Qh, g_Qh);
    cudaGetSymbolAddress((void**)&Kh, g_Kh);
    cudaGetSymbolAddress((void**)&Vh, g_Vh);
    cudaGetSymbolAddress((void**)&Ah, g_Ah);

    SrcPtrs srcs;
    srcs.p[0] = (const float2*)x;
    srcs.p[1] = (const float2*)d_in[1];
    srcs.p[2] = (const float2*)d_in[2];
    srcs.p[3] = (const float2*)d_in[3];
    srcs.p[4] = (const float2*)d_in[4];
    cvt_all_kernel<<<(NALL2 + 255) / 256, 256>>>(srcs);
    cs_kernel<<<(S_LEN * 32 + 255) / 256, 256>>>(pos);

    // merged QKV GEMM with fused RoPE epilogue
    OutPtrs qkv; qkv.p[0] = Qh; qkv.p[1] = Kh; qkv.p[2] = Vh;
    dim3 qkv_grid(3 * DM / HBN, S_LEN / HBM);     // (24, 32)
    hgemm<__half, true><<<qkv_grid, 256>>>(Xh, Wh, qkv);

    flash_h<<<(S_LEN / 64) * NHEADS, 128>>>(Qh, Kh, Vh, Ah);

    OutPtrs op; op.p[0] = out; op.p[1] = out; op.p[2] = out;
    dim3 out_grid(DM / HBN, S_LEN / HBM);         // (8, 32)
    hgemm<float, false><<<out_grid, 256>>>(Ah, Wh + 3 * DM * DM, op);
}

// round 8
// speedup vs baseline: 8.8463x; 1.0002x over previous
#include <cuda_runtime.h>
#include <math.h>
#include <cstdint>
#include <cuda_fp16.h>

#define S_LEN    4096
#define DM       1024
#define NHEADS   16
#define HDIM     64

// Scratch (allocation-free rule: __device__ globals)
__device__ __half g_Xh[S_LEN * DM];
__device__ __half g_Wh[4 * DM * DM];
__device__ __half g_Qh[S_LEN * DM];
__device__ __half g_Kh[S_LEN * DM];
__device__ __half g_Vh[S_LEN * DM];
__device__ __half g_Ah[S_LEN * DM];
__device__ float2 g_cs[S_LEN * 32];        // (cos, sin) per (pos, j)

struct OutPtrs { void* p[3]; };
struct SrcPtrs { const float2* p[5]; };

// ===========================================================================
// Helpers
// ===========================================================================
__device__ __forceinline__ uint32_t smem_u32(const void* p) {
    uint32_t a;
    asm("{ .reg .u64 t; cvta.to.shared.u64 t, %1; cvt.u32.u64 %0, t; }"
        : "=r"(a) : "l"(p));
    return a;
}
__device__ __forceinline__ void cp_async16(uint32_t s, const void* g) {
    asm volatile("cp.async.cg.shared.global [%0], [%1], 16;" :: "r"(s), "l"(g));
}
#define CP_ASYNC_COMMIT()  asm volatile("cp.async.commit_group;" ::: "memory")
#define CP_ASYNC_WAIT(n)   asm volatile("cp.async.wait_group %0;" :: "n"(n) : "memory")

__device__ __forceinline__ void mma_f16(float* c, uint32_t a0, uint32_t a1,
                                        uint32_t a2, uint32_t a3,
                                        uint32_t b0, uint32_t b1) {
    asm volatile(
        "mma.sync.aligned.m16n8k16.row.col.f32.f16.f16.f32 "
        "{%0,%1,%2,%3}, {%4,%5,%6,%7}, {%8,%9}, {%0,%1,%2,%3};"
        : "+f"(c[0]), "+f"(c[1]), "+f"(c[2]), "+f"(c[3])
        : "r"(a0), "r"(a1), "r"(a2), "r"(a3), "r"(b0), "r"(b1));
}
__device__ __forceinline__ void ldmatrix_x4(uint32_t& r0, uint32_t& r1,
                                            uint32_t& r2, uint32_t& r3, uint32_t addr) {
    asm volatile("ldmatrix.sync.aligned.m8n8.x4.shared.b16 {%0,%1,%2,%3}, [%4];"
                 : "=r"(r0), "=r"(r1), "=r"(r2), "=r"(r3) : "r"(addr));
}
__device__ __forceinline__ void ldmatrix_x4_trans(uint32_t& r0, uint32_t& r1,
                                                  uint32_t& r2, uint32_t& r3, uint32_t addr) {
    asm volatile("ldmatrix.sync.aligned.m8n8.x4.trans.shared.b16 {%0,%1,%2,%3}, [%4];"
                 : "=r"(r0), "=r"(r1), "=r"(r2), "=r"(r3) : "r"(addr));
}
__device__ __forceinline__ uint32_t h2pack(float lo, float hi) {
    __half2 h = __floats2half2_rn(lo, hi);
    return *(uint32_t*)&h;
}

// ===========================================================================
// One-shot conversion of x + 4 weights to fp16 (single launch)
// ===========================================================================
#define NX2 (S_LEN * DM / 2)
#define NW2 (DM * DM / 2)
#define NALL2 (NX2 + 4 * NW2)

__global__ __launch_bounds__(256) void cvt_all_kernel(SrcPtrs srcs)
{
    int i = blockIdx.x * blockDim.x + threadIdx.x;
    if (i >= NALL2) return;
    float2 v;
    __half2* dst;
    if (i < NX2) {
        v = srcs.p[0][i];
        dst = (__half2*)g_Xh + i;
    } else {
        int rel = i - NX2;
        int w = rel / NW2;
        int off = rel - w * NW2;
        v = srcs.p[1 + w][off];
        dst = (__half2*)g_Wh + w * NW2 + off;
    }
    *dst = __floats2half2_rn(v.x, v.y);
}

// ---------------------------------------------------------------------------
// cos/sin table: g_cs[s*32 + j] = (cos, sin)(pos[s] * theta^{-j/32})
// ---------------------------------------------------------------------------
__global__ __launch_bounds__(256) void cs_kernel(const int* __restrict__ pos)
{
    int idx = blockIdx.x * blockDim.x + threadIdx.x;
    if (idx >= S_LEN * 32) return;
    int s = idx >> 5;
    int j = idx & 31;
    double invf = exp(-(double)j / 32.0 * log(10000.0));
    float ang = (float)pos[s] * (float)invf;
    float sn, cs;
    sincosf(ang, &sn, &cs);
    g_cs[idx] = make_float2(cs, sn);
}

// ===========================================================================
// fp16 mma.sync GEMM (NT), fp32 accumulate, 128x128x32h tile, 256 threads.
// ROPE=true fuses RoPE into the epilogue; Q additionally gets the
// (1/8)*log2(e) prescale so flash softmax runs in base 2.
// ===========================================================================
#define HBM 128
#define HBN 128
#define HBK 32
#define HKT (DM / HBK)
#define HSTR 40

template <typename OutT, bool ROPE>
__global__ __launch_bounds__(256) void hgemm(
    const __half* __restrict__ A, const __half* __restrict__ B, OutPtrs outs)
{
    __shared__ __align__(16) __half Ah[2][HBM][HSTR];
    __shared__ __align__(16) __half Bh[2][HBN][HSTR];
    const uint32_t ah_u = smem_u32(Ah);
    const uint32_t bh_u = smem_u32(Bh);

    const int tid  = threadIdx.x;
    const int wid  = tid >> 5;
    const int lane = tid & 31;
    const int wm   = wid >> 1;
    const int wn   = wid & 1;
    const int r    = lane >> 2;
    const int c4   = lane & 3;
    const int row0  = blockIdx.y * HBM;
    const int col0g = blockIdx.x * HBN;

    const int mat = col0g >> 10;
    OutT* C = (OutT*)outs.p[mat];
    const int colW = col0g & (DM - 1);

    const int lrow = ((lane >> 3) & 1) * 8 + (lane & 7);
    const int lcol = ((lane >> 4) & 1) * 8;

    float acc[2][8][4];
#pragma unroll
    for (int mt = 0; mt < 2; mt++)
#pragma unroll
        for (int nt = 0; nt < 8; nt++)
#pragma unroll
            for (int i = 0; i < 4; i++) acc[mt][nt][i] = 0.f;

    auto load_tile = [&](int kt, int buf) {
        const int k0 = kt * HBK;
#pragma unroll
        for (int i = 0; i < 2; i++) {
            int chunk = tid + i * 256;
            int m = chunk >> 2, c8 = (chunk & 3) * 8;
            cp_async16(ah_u + (uint32_t)((((buf * HBM) + m) * HSTR + c8) * 2),
                       A + (size_t)(row0 + m) * DM + k0 + c8);
        }
#pragma unroll
        for (int i = 0; i < 2; i++) {
            int chunk = tid + i * 256;
            int m = chunk >> 2, c8 = (chunk & 3) * 8;
            cp_async16(bh_u + (uint32_t)((((buf * HBN) + m) * HSTR + c8) * 2),
                       B + (size_t)(col0g + m) * DM + k0 + c8);
        }
        CP_ASYNC_COMMIT();
    };

    load_tile(0, 0);

    for (int kt = 0; kt < HKT; kt++) {
        const int buf = kt & 1;
        CP_ASYNC_WAIT(0);
        __syncthreads();
        if (kt + 1 < HKT) load_tile(kt + 1, buf ^ 1);

#pragma unroll
        for (int s = 0; s < 2; s++) {
            const int k0 = s * 16;
            uint32_t au[2][4], bu[8][2];
#pragma unroll
            for (int mt = 0; mt < 2; mt++) {
                int row = wm * 32 + mt * 16 + lrow;
                uint32_t addr = ah_u +
                    (uint32_t)(((buf * HBM + row) * HSTR + k0 + lcol) * 2);
                ldmatrix_x4(au[mt][0], au[mt][1], au[mt][2], au[mt][3], addr);
            }
#pragma unroll
            for (int ntp = 0; ntp < 4; ntp++) {
                int row = wn * 64 + ntp * 16 + lrow;
                uint32_t addr = bh_u +
                    (uint32_t)(((buf * HBN + row) * HSTR + k0 + lcol) * 2);
                uint32_t t0, t1, t2, t3;
                ldmatrix_x4(t0, t1, t2, t3, addr);
                bu[2 * ntp][0] = t0;     bu[2 * ntp][1] = t2;
                bu[2 * ntp + 1][0] = t1; bu[2 * ntp + 1][1] = t3;
            }
#pragma unroll
            for (int mt = 0; mt < 2; mt++)
#pragma unroll
                for (int nt = 0; nt < 8; nt++)
                    mma_f16(acc[mt][nt], au[mt][0], au[mt][1], au[mt][2], au[mt][3],
                            bu[nt][0], bu[nt][1]);
        }
    }

    const bool do_rope = ROPE && (mat < 2);
    // Q: 1/8 softmax scale folded with log2(e) for base-2 softmax in flash
    const float qs = (mat == 0) ? 0.125f * 1.4426950408889634f : 1.0f;

#pragma unroll
    for (int mt = 0; mt < 2; mt++) {
#pragma unroll
        for (int nt = 0; nt < 8; nt++) {
            int row = row0 + wm * 32 + mt * 16 + r;
            int col = colW + wn * 64 + nt * 8 + c4 * 2;
            float v0 = acc[mt][nt][0], v1 = acc[mt][nt][1];
            float v2 = acc[mt][nt][2], v3 = acc[mt][nt][3];
            if (do_rope) {
                int j = nt * 4 + c4;
                float2 csA = g_cs[row * 32 + j];
                float2 csB = g_cs[(row + 8) * 32 + j];
                float t0 = v0 * csA.x - v1 * csA.y;
                float t1 = v0 * csA.y + v1 * csA.x;
                float t2 = v2 * csB.x - v3 * csB.y;
                float t3 = v2 * csB.y + v3 * csB.x;
                v0 = t0 * qs; v1 = t1 * qs; v2 = t2 * qs; v3 = t3 * qs;
            }
            if (sizeof(OutT) == 4) {
                *(float2*)((float*)C + (size_t)row * DM + col) = make_float2(v0, v1);
                *(float2*)((float*)C + (size_t)(row + 8) * DM + col) = make_float2(v2, v3);
            } else {
                *(__half2*)((__half*)C + (size_t)row * DM + col) =
                    __floats2half2_rn(v0, v1);
                *(__half2*)((__half*)C + (size_t)(row + 8) * DM + col) =
                    __floats2half2_rn(v2, v3);
            }
        }
    }
}

// ===========================================================================
// fp16 causal flash attention. Bq=128 (8 warps x 16 queries), Bc=64.
// Q pre-scaled by (1/8)*log2(e) -> base-2 softmax, no per-tile scaling.
// V B-frags via ldmatrix.x4.trans (2 col-blocks per instruction).
// ===========================================================================
#define FSTR 72

__global__ __launch_bounds__(256) void flash_h(
    const __half* __restrict__ Q, const __half* __restrict__ K,
    const __half* __restrict__ V, __half* __restrict__ O)
{
    __shared__ __align__(16) __half Ks[2][64][FSTR];
    __shared__ __align__(16) __half Vs[2][64][FSTR];
    const uint32_t ks_u = smem_u32(Ks);
    const uint32_t vs_u = smem_u32(Vs);

    const int tid  = threadIdx.x;
    const int warp = tid >> 5;       // 0..7
    const int lane = tid & 31;
    const int r    = lane >> 2;
    const int c    = lane & 3;
    const int qblk = (gridDim.x >> 4) - 1 - (int)(blockIdx.x >> 4);  // heavy first
    const int h    = blockIdx.x & 15;
    const int qbase = qblk * 128;
    const int w16   = warp * 16;
    const int lrow  = ((lane >> 3) & 1) * 8 + (lane & 7);
    const int lcol  = ((lane >> 4) & 1) * 8;

    // ---- stage 128 Q rows across both Ks buffers, extract A-frags ---------
    for (int i = 0; i < 4; i++) {
        int chunk = tid + i * 256;
        int row = chunk >> 3, c8 = (chunk & 7) * 8;     // row 0..127
        *(float4*)&Ks[0][0][row * FSTR + c8] =
            *(const float4*)(Q + (size_t)(qbase + row) * DM + h * HDIM + c8);
    }
    __syncthreads();

    uint32_t qa[4][4];
#pragma unroll
    for (int g = 0; g < 4; g++) {
        uint32_t addr = ks_u + (uint32_t)(((w16 + lrow) * FSTR + g * 16 + lcol) * 2);
        ldmatrix_x4(qa[g][0], qa[g][1], qa[g][2], qa[g][3], addr);
    }
    __syncthreads();

    auto load_tile = [&](int buf, int kt) {
#pragma unroll
        for (int i = 0; i < 2; i++) {                 // K: 512 chunks, 256 thr
            int chunk = tid + i * 256;
            int row = chunk >> 3, c8 = (chunk & 7) * 8;
            cp_async16(ks_u + (uint32_t)(((buf * 64 + row) * FSTR + c8) * 2),
                       K + (size_t)(kt + row) * DM + h * HDIM + c8);
        }
#pragma unroll
        for (int i = 0; i < 2; i++) {                 // V: 512 chunks
            int chunk = tid + i * 256;
            int row = chunk >> 3, c8 = (chunk & 7) * 8;
            cp_async16(vs_u + (uint32_t)(((buf * 64 + row) * FSTR + c8) * 2),
                       V + (size_t)(kt + row) * DM + h * HDIM + c8);
        }
        CP_ASYNC_COMMIT();
    };

    float acc[8][4];
#pragma unroll
    for (int nt = 0; nt < 8; nt++)
#pragma unroll
        for (int i = 0; i < 4; i++) acc[nt][i] = 0.f;
    float m0 = -1e30f, m1 = -1e30f, l0 = 0.f, l1 = 0.f;

    load_tile(0, 0);
    const int kend = qbase + 128;

    for (int kt = 0; kt < kend; kt += 64) {
        const int buf = (kt >> 6) & 1;
        CP_ASYNC_WAIT(0);
        __syncthreads();
        if (kt + 64 < kend) load_tile(buf ^ 1, kt + 64);

        // warp fully above the diagonal on this tile -> nothing visible
        if (kt > qbase + w16 + 15) continue;

        const uint32_t kb_u = ks_u + (uint32_t)(buf * 64 * FSTR * 2);
        const uint32_t vb_u = vs_u + (uint32_t)(buf * 64 * FSTR * 2);

        // ---- S = Q K^T (already log2-scaled via Q) -------------------------
        float sc[8][4];
#pragma unroll
        for (int nt = 0; nt < 8; nt++)
            sc[nt][0] = sc[nt][1] = sc[nt][2] = sc[nt][3] = 0.f;
#pragma unroll
        for (int g = 0; g < 4; g++) {
#pragma unroll
            for (int ntp = 0; ntp < 4; ntp++) {
                uint32_t addr = kb_u +
                    (uint32_t)(((ntp * 16 + lrow) * FSTR + g * 16 + lcol) * 2);
                uint32_t t0, t1, t2, t3;
                ldmatrix_x4(t0, t1, t2, t3, addr);
                mma_f16(sc[2 * ntp],     qa[g][0], qa[g][1], qa[g][2], qa[g][3], t0, t2);
                mma_f16(sc[2 * ntp + 1], qa[g][0], qa[g][1], qa[g][2], qa[g][3], t1, t3);
            }
        }

        // ---- causal mask (diagonal tiles only) -----------------------------
        if (kt + 63 > qbase + w16) {
            const int thr0 = qbase + w16 + r - kt;     // max visible local col
            const int thr1 = thr0 + 8;
#pragma unroll
            for (int nt = 0; nt < 8; nt++) {
                int cb = nt * 8 + 2 * c;
                if (cb     > thr0) sc[nt][0] = -1e30f;
                if (cb + 1 > thr0) sc[nt][1] = -1e30f;
                if (cb     > thr1) sc[nt][2] = -1e30f;
                if (cb + 1 > thr1) sc[nt][3] = -1e30f;
            }
        }

        // ---- online softmax (base-2) --------------------------------------
        float mx0 = -1e30f, mx1 = -1e30f;
#pragma unroll
        for (int nt = 0; nt < 8; nt++) {
            mx0 = fmaxf(mx0, fmaxf(sc[nt][0], sc[nt][1]));
            mx1 = fmaxf(mx1, fmaxf(sc[nt][2], sc[nt][3]));
        }
        mx0 = fmaxf(mx0, __shfl_xor_sync(0xffffffffu, mx0, 1));
        mx0 = fmaxf(mx0, __shfl_xor_sync(0xffffffffu, mx0, 2));
        mx1 = fmaxf(mx1, __shfl_xor_sync(0xffffffffu, mx1, 1));
        mx1 = fmaxf(mx1, __shfl_xor_sync(0xffffffffu, mx1, 2));

        float nm0 = fmaxf(m0, mx0), nm1 = fmaxf(m1, mx1);
        float s0 = exp2f(m0 - nm0), s1 = exp2f(m1 - nm1);
        m0 = nm0; m1 = nm1;

        float rs0 = 0.f, rs1 = 0.f;
#pragma unroll
        for (int nt = 0; nt < 8; nt++) {
            sc[nt][0] = exp2f(sc[nt][0] - nm0);
            sc[nt][1] = exp2f(sc[nt][1] - nm0);
            sc[nt][2] = exp2f(sc[nt][2] - nm1);
            sc[nt][3] = exp2f(sc[nt][3] - nm1);
            rs0 += sc[nt][0] + sc[nt][1];
            rs1 += sc[nt][2] + sc[nt][3];
        }
        rs0 += __shfl_xor_sync(0xffffffffu, rs0, 1);
        rs0 += __shfl_xor_sync(0xffffffffu, rs0, 2);
        rs1 += __shfl_xor_sync(0xffffffffu, rs1, 1);
        rs1 += __shfl_xor_sync(0xffffffffu, rs1, 2);
        l0 = l0 * s0 + rs0;
        l1 = l1 * s1 + rs1;

#pragma unroll
        for (int nt = 0; nt < 8; nt++) {
            acc[nt][0] *= s0; acc[nt][1] *= s0;
            acc[nt][2] *= s1; acc[nt][3] *= s1;
        }

        // ---- O += P.V  (V via ldmatrix.x4.trans, 2 col-blocks per op) -----
#pragma unroll
        for (int kk = 0; kk < 4; kk++) {
            uint32_t a0 = h2pack(sc[2 * kk][0],     sc[2 * kk][1]);
            uint32_t a1 = h2pack(sc[2 * kk][2],     sc[2 * kk][3]);
            uint32_t a2 = h2pack(sc[2 * kk + 1][0], sc[2 * kk + 1][1]);
            uint32_t a3 = h2pack(sc[2 * kk + 1][2], sc[2 * kk + 1][3]);
            const int vrow = kk * 16 + (lane & 15);
            const int vcolsel = (lane >> 4) & 1;
#pragma unroll
            for (int ndp = 0; ndp < 4; ndp++) {
                uint32_t baddr = vb_u +
                    (uint32_t)((vrow * FSTR + (2 * ndp + vcolsel) * 8) * 2);
                uint32_t b0, b1, b2, b3;
                ldmatrix_x4_trans(b0, b1, b2, b3, baddr);
                mma_f16(acc[2 * ndp],     a0, a1, a2, a3, b0, b1);
                mma_f16(acc[2 * ndp + 1], a0, a1, a2, a3, b2, b3);
            }
        }
    }

    // ---- epilogue ---------------------------------------------------------
    float i0 = 1.f / l0, i1 = 1.f / l1;
    const int row0 = qbase + w16 + r;
#pragma unroll
    for (int nt = 0; nt < 8; nt++) {
        int col = h * HDIM + nt * 8 + 2 * c;
        *(__half2*)&O[(size_t)row0 * DM + col] =
            __floats2half2_rn(acc[nt][0] * i0, acc[nt][1] * i0);
        *(__half2*)&O[(size_t)(row0 + 8) * DM + col] =
            __floats2half2_rn(acc[nt][2] * i1, acc[nt][3] * i1);
    }
}

// ---------------------------------------------------------------------------
// Launcher
// ---------------------------------------------------------------------------
extern "C" void kernel_launch(void* const* d_in, const int* in_sizes, int n_in,
                              void* d_out, int out_size)
{
    const float* x  = (const float*)d_in[0];
    const int*  pos = (const int*)  d_in[5];
    float* out = (float*)d_out;

    __half *Xh, *Wh, *Qh, *Kh, *Vh, *Ah;
    cudaGetSymbolAddress((void**)&Xh, g_Xh);
    cudaGetSymbolAddress((void**)&Wh, g_Wh);
    cudaGetSymbolAddress((void**)&Qh, g_Qh);
    cudaGetSymbolAddress((void**)&Kh, g_Kh);
    cudaGetSymbolAddress((void**)&Vh, g_Vh);
    cudaGetSymbolAddress((void**)&Ah, g_Ah);

    SrcPtrs srcs;
    srcs.p[0] = (const float2*)x;
    srcs.p[1] = (const float2*)d_in[1];
    srcs.p[2] = (const float2*)d_in[2];
    srcs.p[3] = (const float2*)d_in[3];
    srcs.p[4] = (const float2*)d_in[4];
    cvt_all_kernel<<<(NALL2 + 255) / 256, 256>>>(srcs);
    cs_kernel<<<(S_LEN * 32 + 255) / 256, 256>>>(pos);

    // merged QKV GEMM with fused RoPE (+ base-2 Q prescale) epilogue
    OutPtrs qkv; qkv.p[0] = Qh; qkv.p[1] = Kh; qkv.p[2] = Vh;
    dim3 qkv_grid(3 * DM / HBN, S_LEN / HBM);     // (24, 32)
    hgemm<__half, true><<<qkv_grid, 256>>>(Xh, Wh, qkv);

    flash_h<<<(S_LEN / 128) * NHEADS, 256>>>(Qh, Kh, Vh, Ah);

    OutPtrs op; op.p[0] = out; op.p[1] = out; op.p[2] = out;
    dim3 out_grid(DM / HBN, S_LEN / HBM);         // (8, 32)
    hgemm<float, false><<<out_grid, 256>>>(Ah, Wh + 3 * DM * DM, op);
}

// round 9
// speedup vs baseline: 9.1281x; 1.0319x over previous
#include <cuda_runtime.h>
#include <math.h>
#include <cstdint>
#include <cuda_fp16.h>

#define S_LEN    4096
#define DM       1024
#define NHEADS   16
#define HDIM     64

// Scratch (allocation-free rule: __device__ globals)
__device__ __half g_Xh[S_LEN * DM];
__device__ __half g_Wh[4 * DM * DM];
__device__ __half g_Qh[S_LEN * DM];
__device__ __half g_Kh[S_LEN * DM];
__device__ __half g_Vh[S_LEN * DM];
__device__ __half g_Ah[S_LEN * DM];
__device__ float2 g_cs[S_LEN * 32];        // (cos, sin) per (pos, j)

struct OutPtrs { void* p[3]; };
struct SrcPtrs { const float2* p[5]; };

// ===========================================================================
// Helpers
// ===========================================================================
__device__ __forceinline__ uint32_t smem_u32(const void* p) {
    uint32_t a;
    asm("{ .reg .u64 t; cvta.to.shared.u64 t, %1; cvt.u32.u64 %0, t; }"
        : "=r"(a) : "l"(p));
    return a;
}
__device__ __forceinline__ void cp_async16(uint32_t s, const void* g) {
    asm volatile("cp.async.cg.shared.global [%0], [%1], 16;" :: "r"(s), "l"(g));
}
#define CP_ASYNC_COMMIT()  asm volatile("cp.async.commit_group;" ::: "memory")
#define CP_ASYNC_WAIT(n)   asm volatile("cp.async.wait_group %0;" :: "n"(n) : "memory")

__device__ __forceinline__ void mma_f16(float* c, uint32_t a0, uint32_t a1,
                                        uint32_t a2, uint32_t a3,
                                        uint32_t b0, uint32_t b1) {
    asm volatile(
        "mma.sync.aligned.m16n8k16.row.col.f32.f16.f16.f32 "
        "{%0,%1,%2,%3}, {%4,%5,%6,%7}, {%8,%9}, {%0,%1,%2,%3};"
        : "+f"(c[0]), "+f"(c[1]), "+f"(c[2]), "+f"(c[3])
        : "r"(a0), "r"(a1), "r"(a2), "r"(a3), "r"(b0), "r"(b1));
}
__device__ __forceinline__ void ldmatrix_x4(uint32_t& r0, uint32_t& r1,
                                            uint32_t& r2, uint32_t& r3, uint32_t addr) {
    asm volatile("ldmatrix.sync.aligned.m8n8.x4.shared.b16 {%0,%1,%2,%3}, [%4];"
                 : "=r"(r0), "=r"(r1), "=r"(r2), "=r"(r3) : "r"(addr));
}
__device__ __forceinline__ void ldmatrix_x4_trans(uint32_t& r0, uint32_t& r1,
                                                  uint32_t& r2, uint32_t& r3, uint32_t addr) {
    asm volatile("ldmatrix.sync.aligned.m8n8.x4.trans.shared.b16 {%0,%1,%2,%3}, [%4];"
                 : "=r"(r0), "=r"(r1), "=r"(r2), "=r"(r3) : "r"(addr));
}
// pack (x, y) to half2, then 2^x in packed fp16
__device__ __forceinline__ uint32_t ex2_h2(float x, float y) {
    __half2 h = __floats2half2_rn(x, y);
    uint32_t d = *(uint32_t*)&h;
    uint32_t p;
    asm("ex2.approx.f16x2 %0, %1;" : "=r"(p) : "r"(d));
    return p;
}

// ===========================================================================
// One-shot conversion of x + 4 weights to fp16 (single launch)
// ===========================================================================
#define NX2 (S_LEN * DM / 2)
#define NW2 (DM * DM / 2)
#define NALL2 (NX2 + 4 * NW2)

__global__ __launch_bounds__(256) void cvt_all_kernel(SrcPtrs srcs)
{
    int i = blockIdx.x * blockDim.x + threadIdx.x;
    if (i >= NALL2) return;
    float2 v;
    __half2* dst;
    if (i < NX2) {
        v = srcs.p[0][i];
        dst = (__half2*)g_Xh + i;
    } else {
        int rel = i - NX2;
        int w = rel / NW2;
        int off = rel - w * NW2;
        v = srcs.p[1 + w][off];
        dst = (__half2*)g_Wh + w * NW2 + off;
    }
    *dst = __floats2half2_rn(v.x, v.y);
}

// ---------------------------------------------------------------------------
// cos/sin table: g_cs[s*32 + j] = (cos, sin)(pos[s] * theta^{-j/32})
// ---------------------------------------------------------------------------
__global__ __launch_bounds__(256) void cs_kernel(const int* __restrict__ pos)
{
    int idx = blockIdx.x * blockDim.x + threadIdx.x;
    if (idx >= S_LEN * 32) return;
    int s = idx >> 5;
    int j = idx & 31;
    double invf = exp(-(double)j / 32.0 * log(10000.0));
    float ang = (float)pos[s] * (float)invf;
    float sn, cs;
    sincosf(ang, &sn, &cs);
    g_cs[idx] = make_float2(cs, sn);
}

// ===========================================================================
// fp16 mma.sync GEMM (NT), fp32 accumulate, 128x128x32h tile, 256 threads.
// ROPE=true fuses RoPE into the epilogue; Q additionally gets the
// (1/8)*log2(e) prescale so flash softmax runs in base 2.
// ===========================================================================
#define HBM 128
#define HBN 128
#define HBK 32
#define HKT (DM / HBK)
#define HSTR 40

template <typename OutT, bool ROPE>
__global__ __launch_bounds__(256) void hgemm(
    const __half* __restrict__ A, const __half* __restrict__ B, OutPtrs outs)
{
    __shared__ __align__(16) __half Ah[2][HBM][HSTR];
    __shared__ __align__(16) __half Bh[2][HBN][HSTR];
    const uint32_t ah_u = smem_u32(Ah);
    const uint32_t bh_u = smem_u32(Bh);

    const int tid  = threadIdx.x;
    const int wid  = tid >> 5;
    const int lane = tid & 31;
    const int wm   = wid >> 1;
    const int wn   = wid & 1;
    const int r    = lane >> 2;
    const int c4   = lane & 3;
    const int row0  = blockIdx.y * HBM;
    const int col0g = blockIdx.x * HBN;

    const int mat = col0g >> 10;
    OutT* C = (OutT*)outs.p[mat];
    const int colW = col0g & (DM - 1);

    const int lrow = ((lane >> 3) & 1) * 8 + (lane & 7);
    const int lcol = ((lane >> 4) & 1) * 8;

    float acc[2][8][4];
#pragma unroll
    for (int mt = 0; mt < 2; mt++)
#pragma unroll
        for (int nt = 0; nt < 8; nt++)
#pragma unroll
            for (int i = 0; i < 4; i++) acc[mt][nt][i] = 0.f;

    auto load_tile = [&](int kt, int buf) {
        const int k0 = kt * HBK;
#pragma unroll
        for (int i = 0; i < 2; i++) {
            int chunk = tid + i * 256;
            int m = chunk >> 2, c8 = (chunk & 3) * 8;
            cp_async16(ah_u + (uint32_t)((((buf * HBM) + m) * HSTR + c8) * 2),
                       A + (size_t)(row0 + m) * DM + k0 + c8);
        }
#pragma unroll
        for (int i = 0; i < 2; i++) {
            int chunk = tid + i * 256;
            int m = chunk >> 2, c8 = (chunk & 3) * 8;
            cp_async16(bh_u + (uint32_t)((((buf * HBN) + m) * HSTR + c8) * 2),
                       B + (size_t)(col0g + m) * DM + k0 + c8);
        }
        CP_ASYNC_COMMIT();
    };

    load_tile(0, 0);

    for (int kt = 0; kt < HKT; kt++) {
        const int buf = kt & 1;
        CP_ASYNC_WAIT(0);
        __syncthreads();
        if (kt + 1 < HKT) load_tile(kt + 1, buf ^ 1);

#pragma unroll
        for (int s = 0; s < 2; s++) {
            const int k0 = s * 16;
            uint32_t au[2][4], bu[8][2];
#pragma unroll
            for (int mt = 0; mt < 2; mt++) {
                int row = wm * 32 + mt * 16 + lrow;
                uint32_t addr = ah_u +
                    (uint32_t)(((buf * HBM + row) * HSTR + k0 + lcol) * 2);
                ldmatrix_x4(au[mt][0], au[mt][1], au[mt][2], au[mt][3], addr);
            }
#pragma unroll
            for (int ntp = 0; ntp < 4; ntp++) {
                int row = wn * 64 + ntp * 16 + lrow;
                uint32_t addr = bh_u +
                    (uint32_t)(((buf * HBN + row) * HSTR + k0 + lcol) * 2);
                uint32_t t0, t1, t2, t3;
                ldmatrix_x4(t0, t1, t2, t3, addr);
                bu[2 * ntp][0] = t0;     bu[2 * ntp][1] = t2;
                bu[2 * ntp + 1][0] = t1; bu[2 * ntp + 1][1] = t3;
            }
#pragma unroll
            for (int mt = 0; mt < 2; mt++)
#pragma unroll
                for (int nt = 0; nt < 8; nt++)
                    mma_f16(acc[mt][nt], au[mt][0], au[mt][1], au[mt][2], au[mt][3],
                            bu[nt][0], bu[nt][1]);
        }
    }

    const bool do_rope = ROPE && (mat < 2);
    // Q: 1/8 softmax scale folded with log2(e) for base-2 softmax in flash
    const float qs = (mat == 0) ? 0.125f * 1.4426950408889634f : 1.0f;

#pragma unroll
    for (int mt = 0; mt < 2; mt++) {
#pragma unroll
        for (int nt = 0; nt < 8; nt++) {
            int row = row0 + wm * 32 + mt * 16 + r;
            int col = colW + wn * 64 + nt * 8 + c4 * 2;
            float v0 = acc[mt][nt][0], v1 = acc[mt][nt][1];
            float v2 = acc[mt][nt][2], v3 = acc[mt][nt][3];
            if (do_rope) {
                int j = nt * 4 + c4;
                float2 csA = g_cs[row * 32 + j];
                float2 csB = g_cs[(row + 8) * 32 + j];
                float t0 = v0 * csA.x - v1 * csA.y;
                float t1 = v0 * csA.y + v1 * csA.x;
                float t2 = v2 * csB.x - v3 * csB.y;
                float t3 = v2 * csB.y + v3 * csB.x;
                v0 = t0 * qs; v1 = t1 * qs; v2 = t2 * qs; v3 = t3 * qs;
            }
            if (sizeof(OutT) == 4) {
                *(float2*)((float*)C + (size_t)row * DM + col) = make_float2(v0, v1);
                *(float2*)((float*)C + (size_t)(row + 8) * DM + col) = make_float2(v2, v3);
            } else {
                *(__half2*)((__half*)C + (size_t)row * DM + col) =
                    __floats2half2_rn(v0, v1);
                *(__half2*)((__half*)C + (size_t)(row + 8) * DM + col) =
                    __floats2half2_rn(v2, v3);
            }
        }
    }
}

// ===========================================================================
// fp16 causal flash attention. Bq=128 (8 warps x 16 queries), Bc=64.
// Base-2 softmax with packed ex2.approx.f16x2 (P born as fp16 A-frags);
// row-sum l computed by an extra PV-style MMA against an all-ones B-frag.
// ===========================================================================
#define FSTR 72
#define H2_ONES 0x3C003C00u

__global__ __launch_bounds__(256) void flash_h(
    const __half* __restrict__ Q, const __half* __restrict__ K,
    const __half* __restrict__ V, __half* __restrict__ O)
{
    __shared__ __align__(16) __half Ks[2][64][FSTR];
    __shared__ __align__(16) __half Vs[2][64][FSTR];
    const uint32_t ks_u = smem_u32(Ks);
    const uint32_t vs_u = smem_u32(Vs);

    const int tid  = threadIdx.x;
    const int warp = tid >> 5;       // 0..7
    const int lane = tid & 31;
    const int r    = lane >> 2;
    const int c    = lane & 3;
    const int qblk = (gridDim.x >> 4) - 1 - (int)(blockIdx.x >> 4);  // heavy first
    const int h    = blockIdx.x & 15;
    const int qbase = qblk * 128;
    const int w16   = warp * 16;
    const int lrow  = ((lane >> 3) & 1) * 8 + (lane & 7);
    const int lcol  = ((lane >> 4) & 1) * 8;

    // ---- stage 128 Q rows across both Ks buffers, extract A-frags ---------
    for (int i = 0; i < 4; i++) {
        int chunk = tid + i * 256;
        int row = chunk >> 3, c8 = (chunk & 7) * 8;     // row 0..127
        *(float4*)&Ks[0][0][row * FSTR + c8] =
            *(const float4*)(Q + (size_t)(qbase + row) * DM + h * HDIM + c8);
    }
    __syncthreads();

    uint32_t qa[4][4];
#pragma unroll
    for (int g = 0; g < 4; g++) {
        uint32_t addr = ks_u + (uint32_t)(((w16 + lrow) * FSTR + g * 16 + lcol) * 2);
        ldmatrix_x4(qa[g][0], qa[g][1], qa[g][2], qa[g][3], addr);
    }
    __syncthreads();

    auto load_tile = [&](int buf, int kt) {
#pragma unroll
        for (int i = 0; i < 2; i++) {
            int chunk = tid + i * 256;
            int row = chunk >> 3, c8 = (chunk & 7) * 8;
            cp_async16(ks_u + (uint32_t)(((buf * 64 + row) * FSTR + c8) * 2),
                       K + (size_t)(kt + row) * DM + h * HDIM + c8);
        }
#pragma unroll
        for (int i = 0; i < 2; i++) {
            int chunk = tid + i * 256;
            int row = chunk >> 3, c8 = (chunk & 7) * 8;
            cp_async16(vs_u + (uint32_t)(((buf * 64 + row) * FSTR + c8) * 2),
                       V + (size_t)(kt + row) * DM + h * HDIM + c8);
        }
        CP_ASYNC_COMMIT();
    };

    float acc[8][4];
#pragma unroll
    for (int nt = 0; nt < 8; nt++)
#pragma unroll
        for (int i = 0; i < 4; i++) acc[nt][i] = 0.f;
    float m0 = -1e30f, m1 = -1e30f, l0 = 0.f, l1 = 0.f;

    load_tile(0, 0);
    const int kend = qbase + 128;

    for (int kt = 0; kt < kend; kt += 64) {
        const int buf = (kt >> 6) & 1;
        CP_ASYNC_WAIT(0);
        __syncthreads();
        if (kt + 64 < kend) load_tile(buf ^ 1, kt + 64);

        // warp fully above the diagonal on this tile -> nothing visible
        if (kt > qbase + w16 + 15) continue;

        const uint32_t kb_u = ks_u + (uint32_t)(buf * 64 * FSTR * 2);
        const uint32_t vb_u = vs_u + (uint32_t)(buf * 64 * FSTR * 2);

        // ---- S = Q K^T (already log2-scaled via Q) -------------------------
        float sc[8][4];
#pragma unroll
        for (int nt = 0; nt < 8; nt++)
            sc[nt][0] = sc[nt][1] = sc[nt][2] = sc[nt][3] = 0.f;
#pragma unroll
        for (int g = 0; g < 4; g++) {
#pragma unroll
            for (int ntp = 0; ntp < 4; ntp++) {
                uint32_t addr = kb_u +
                    (uint32_t)(((ntp * 16 + lrow) * FSTR + g * 16 + lcol) * 2);
                uint32_t t0, t1, t2, t3;
                ldmatrix_x4(t0, t1, t2, t3, addr);
                mma_f16(sc[2 * ntp],     qa[g][0], qa[g][1], qa[g][2], qa[g][3], t0, t2);
                mma_f16(sc[2 * ntp + 1], qa[g][0], qa[g][1], qa[g][2], qa[g][3], t1, t3);
            }
        }

        // ---- causal mask (diagonal tiles only) -----------------------------
        if (kt + 63 > qbase + w16) {
            const int thr0 = qbase + w16 + r - kt;     // max visible local col
            const int thr1 = thr0 + 8;
#pragma unroll
            for (int nt = 0; nt < 8; nt++) {
                int cb = nt * 8 + 2 * c;
                if (cb     > thr0) sc[nt][0] = -1e30f;
                if (cb + 1 > thr0) sc[nt][1] = -1e30f;
                if (cb     > thr1) sc[nt][2] = -1e30f;
                if (cb + 1 > thr1) sc[nt][3] = -1e30f;
            }
        }

        // ---- online max (base-2 domain) ------------------------------------
        float mx0 = -1e30f, mx1 = -1e30f;
#pragma unroll
        for (int nt = 0; nt < 8; nt++) {
            mx0 = fmaxf(mx0, fmaxf(sc[nt][0], sc[nt][1]));
            mx1 = fmaxf(mx1, fmaxf(sc[nt][2], sc[nt][3]));
        }
        mx0 = fmaxf(mx0, __shfl_xor_sync(0xffffffffu, mx0, 1));
        mx0 = fmaxf(mx0, __shfl_xor_sync(0xffffffffu, mx0, 2));
        mx1 = fmaxf(mx1, __shfl_xor_sync(0xffffffffu, mx1, 1));
        mx1 = fmaxf(mx1, __shfl_xor_sync(0xffffffffu, mx1, 2));

        float nm0 = fmaxf(m0, mx0), nm1 = fmaxf(m1, mx1);
        float s0 = exp2f(m0 - nm0), s1 = exp2f(m1 - nm1);
        m0 = nm0; m1 = nm1;
        l0 *= s0; l1 *= s1;
#pragma unroll
        for (int nt = 0; nt < 8; nt++) {
            acc[nt][0] *= s0; acc[nt][1] *= s0;
            acc[nt][2] *= s1; acc[nt][3] *= s1;
        }

        // ---- P = ex2(sc - m) in packed fp16; PV + row-sum MMAs -------------
        float lacc[4] = {0.f, 0.f, 0.f, 0.f};
#pragma unroll
        for (int kk = 0; kk < 4; kk++) {
            uint32_t a0 = ex2_h2(sc[2 * kk][0] - m0,     sc[2 * kk][1] - m0);
            uint32_t a1 = ex2_h2(sc[2 * kk][2] - m1,     sc[2 * kk][3] - m1);
            uint32_t a2 = ex2_h2(sc[2 * kk + 1][0] - m0, sc[2 * kk + 1][1] - m0);
            uint32_t a3 = ex2_h2(sc[2 * kk + 1][2] - m1, sc[2 * kk + 1][3] - m1);

            mma_f16(lacc, a0, a1, a2, a3, H2_ONES, H2_ONES);   // row sums

            const int vrow = kk * 16 + (lane & 15);
            const int vcolsel = (lane >> 4) & 1;
#pragma unroll
            for (int ndp = 0; ndp < 4; ndp++) {
                uint32_t baddr = vb_u +
                    (uint32_t)((vrow * FSTR + (2 * ndp + vcolsel) * 8) * 2);
                uint32_t b0, b1, b2, b3;
                ldmatrix_x4_trans(b0, b1, b2, b3, baddr);
                mma_f16(acc[2 * ndp],     a0, a1, a2, a3, b0, b1);
                mma_f16(acc[2 * ndp + 1], a0, a1, a2, a3, b2, b3);
            }
        }
        l0 += lacc[0];
        l1 += lacc[2];
    }

    // ---- epilogue ---------------------------------------------------------
    float i0 = 1.f / l0, i1 = 1.f / l1;
    const int row0 = qbase + w16 + r;
#pragma unroll
    for (int nt = 0; nt < 8; nt++) {
        int col = h * HDIM + nt * 8 + 2 * c;
        *(__half2*)&O[(size_t)row0 * DM + col] =
            __floats2half2_rn(acc[nt][0] * i0, acc[nt][1] * i0);
        *(__half2*)&O[(size_t)(row0 + 8) * DM + col] =
            __floats2half2_rn(acc[nt][2] * i1, acc[nt][3] * i1);
    }
}

// ---------------------------------------------------------------------------
// Launcher
// ---------------------------------------------------------------------------
extern "C" void kernel_launch(void* const* d_in, const int* in_sizes, int n_in,
                              void* d_out, int out_size)
{
    const float* x  = (const float*)d_in[0];
    const int*  pos = (const int*)  d_in[5];
    float* out = (float*)d_out;

    __half *Xh, *Wh, *Qh, *Kh, *Vh, *Ah;
    cudaGetSymbolAddress((void**)&Xh, g_Xh);
    cudaGetSymbolAddress((void**)&Wh, g_Wh);
    cudaGetSymbolAddress((void**)&Qh, g_Qh);
    cudaGetSymbolAddress((void**)&Kh, g_Kh);
    cudaGetSymbolAddress((void**)&Vh, g_Vh);
    cudaGetSymbolAddress((void**)&Ah, g_Ah);

    SrcPtrs srcs;
    srcs.p[0] = (const float2*)x;
    srcs.p[1] = (const float2*)d_in[1];
    srcs.p[2] = (const float2*)d_in[2];
    srcs.p[3] = (const float2*)d_in[3];
    srcs.p[4] = (const float2*)d_in[4];
    cvt_all_kernel<<<(NALL2 + 255) / 256, 256>>>(srcs);
    cs_kernel<<<(S_LEN * 32 + 255) / 256, 256>>>(pos);

    // merged QKV GEMM with fused RoPE (+ base-2 Q prescale) epilogue
    OutPtrs qkv; qkv.p[0] = Qh; qkv.p[1] = Kh; qkv.p[2] = Vh;
    dim3 qkv_grid(3 * DM / HBN, S_LEN / HBM);     // (24, 32)
    hgemm<__half, true><<<qkv_grid, 256>>>(Xh, Wh, qkv);

    flash_h<<<(S_LEN / 128) * NHEADS, 256>>>(Qh, Kh, Vh, Ah);

    OutPtrs op; op.p[0] = out; op.p[1] = out; op.p[2] = out;
    dim3 out_grid(DM / HBN, S_LEN / HBM);         // (8, 32)
    hgemm<float, false><<<out_grid, 256>>>(Ah, Wh + 3 * DM * DM, op);
}